// round 1
// baseline (speedup 1.0000x reference)
#include <cuda_runtime.h>
#include <math.h>

// Problem constants
static const int Bv   = 16;
static const int Sv   = 1024;
static const int Dv   = 512;
static const int Hv   = 8;
static const int DHv  = 64;
static const int DFFv = 2048;
static const int BSv  = Bv * Sv;        // 16384
static const int SDv  = Sv * Dv;        // 524288 = 2^19

// ---------------- scratch (device globals; no allocation allowed) ----------
__device__ float g_q[BSv * Dv];
__device__ float g_k[BSv * Dv];
__device__ float g_v[BSv * Dv];
__device__ float g_ctx[BSv * Dv];
__device__ float g_attnout[BSv * Dv];
__device__ float g_res1[BSv * Dv];
__device__ float g_out1[BSv * Dv];
__device__ float g_ffn[BSv * DFFv];
__device__ float g_ffnout[BSv * Dv];
__device__ float g_res2[BSv * Dv];
__device__ float g_part1[16 * 128 * 2];
__device__ float g_part2[16 * 128 * 2];
__device__ float g_stats1[16 * 2];
__device__ float g_stats2[16 * 2];

// ---------------------------------------------------------------------------
// SGEMM: C[M,N] = A[M,K] @ W[K,N] + bias[N]   (optional ReLU)
// 128x128 block tile, BK=16, 256 threads, 8x8 micro-tile, register prefetch.
// All M,N,K are multiples of the tile dims for this problem -> no guards.
// ---------------------------------------------------------------------------
template <int RELU>
__global__ __launch_bounds__(256) void sgemm_bias(
    const float* __restrict__ A, const float* __restrict__ W,
    const float* __restrict__ bias, float* __restrict__ C,
    int M, int N, int K)
{
    __shared__ float As[16][132];   // padded, stored transposed: As[k][m]
    __shared__ float Bs[16][128];   // Bs[k][n]

    const int tid = threadIdx.x;
    const int tx  = tid & 15;
    const int ty  = tid >> 4;
    const int m0  = blockIdx.y * 128;
    const int n0  = blockIdx.x * 128;

    float acc[8][8];
#pragma unroll
    for (int i = 0; i < 8; i++)
#pragma unroll
        for (int j = 0; j < 8; j++) acc[i][j] = 0.f;

    float4 pa[2], pb[2];

    // prologue load (k0 = 0)
#pragma unroll
    for (int i = 0; i < 2; i++) {
        int idx = tid + i * 256;
        int row = idx >> 2, q = (idx & 3) << 2;
        pa[i] = *(const float4*)(A + (size_t)(m0 + row) * K + q);
    }
#pragma unroll
    for (int i = 0; i < 2; i++) {
        int idx = tid + i * 256;
        int row = idx >> 5, c = (idx & 31) << 2;
        pb[i] = *(const float4*)(W + (size_t)row * N + n0 + c);
    }

    for (int k0 = 0; k0 < K; k0 += 16) {
        __syncthreads();
        // store prefetched tile to smem (A transposed)
#pragma unroll
        for (int i = 0; i < 2; i++) {
            int idx = tid + i * 256;
            int row = idx >> 2, q = (idx & 3) << 2;
            As[q + 0][row] = pa[i].x;
            As[q + 1][row] = pa[i].y;
            As[q + 2][row] = pa[i].z;
            As[q + 3][row] = pa[i].w;
        }
#pragma unroll
        for (int i = 0; i < 2; i++) {
            int idx = tid + i * 256;
            int row = idx >> 5, c = (idx & 31) << 2;
            *(float4*)&Bs[row][c] = pb[i];
        }
        __syncthreads();

        // prefetch next k-tile
        if (k0 + 16 < K) {
            int kn = k0 + 16;
#pragma unroll
            for (int i = 0; i < 2; i++) {
                int idx = tid + i * 256;
                int row = idx >> 2, q = (idx & 3) << 2;
                pa[i] = *(const float4*)(A + (size_t)(m0 + row) * K + kn + q);
            }
#pragma unroll
            for (int i = 0; i < 2; i++) {
                int idx = tid + i * 256;
                int row = idx >> 5, c = (idx & 31) << 2;
                pb[i] = *(const float4*)(W + (size_t)(kn + row) * N + n0 + c);
            }
        }

#pragma unroll
        for (int k = 0; k < 16; k++) {
            float4 a0 = *(float4*)&As[k][ty * 4];
            float4 a1 = *(float4*)&As[k][ty * 4 + 64];
            float4 b0 = *(float4*)&Bs[k][tx * 4];
            float4 b1 = *(float4*)&Bs[k][tx * 4 + 64];
            float av[8] = {a0.x, a0.y, a0.z, a0.w, a1.x, a1.y, a1.z, a1.w};
            float bv[8] = {b0.x, b0.y, b0.z, b0.w, b1.x, b1.y, b1.z, b1.w};
#pragma unroll
            for (int i = 0; i < 8; i++)
#pragma unroll
                for (int j = 0; j < 8; j++)
                    acc[i][j] += av[i] * bv[j];
        }
    }

    // epilogue: bias (+ ReLU), write
#pragma unroll
    for (int g = 0; g < 2; g++) {
#pragma unroll
        for (int rr = 0; rr < 4; rr++) {
            int r = m0 + g * 64 + ty * 4 + rr;
#pragma unroll
            for (int cg = 0; cg < 2; cg++) {
                int c = n0 + cg * 64 + tx * 4;
                float4 bv = *(const float4*)&bias[c];
                float4 v;
                v.x = acc[g * 4 + rr][cg * 4 + 0] + bv.x;
                v.y = acc[g * 4 + rr][cg * 4 + 1] + bv.y;
                v.z = acc[g * 4 + rr][cg * 4 + 2] + bv.z;
                v.w = acc[g * 4 + rr][cg * 4 + 3] + bv.w;
                if (RELU) {
                    v.x = fmaxf(v.x, 0.f); v.y = fmaxf(v.y, 0.f);
                    v.z = fmaxf(v.z, 0.f); v.w = fmaxf(v.w, 0.f);
                }
                *(float4*)(C + (size_t)r * N + c) = v;
            }
        }
    }
}

// ---------------------------------------------------------------------------
// Flash attention (fp32). grid = (S/64, B*H), block = 256.
// Q,K,V,O laid out as [B*S, D] with head slice at column h*64.
// ---------------------------------------------------------------------------
#define ATT_PAD 68
#define ATT_SMEM (4 * 64 * ATT_PAD * 4)

__global__ __launch_bounds__(256) void attn_kernel(
    const float* __restrict__ Q, const float* __restrict__ K,
    const float* __restrict__ V, const float* __restrict__ mask,
    float* __restrict__ O)
{
    extern __shared__ float sm[];
    float* Qs = sm;
    float* Ks = Qs + 64 * ATT_PAD;
    float* Vs = Ks + 64 * ATT_PAD;
    float* Ps = Vs + 64 * ATT_PAD;

    const int tid = threadIdx.x;
    const int tx  = tid & 15;
    const int ty  = tid >> 4;
    const int qt  = blockIdx.x;
    const int bh  = blockIdx.y;
    const int b   = bh >> 3;
    const int h   = bh & 7;

    const size_t hcol = (size_t)h * DHv;
    const size_t brow = (size_t)b * Sv;

    // load Q tile [64 x 64]
#pragma unroll
    for (int i = 0; i < 4; i++) {
        int idx = tid + i * 256;
        int row = idx >> 4, c4 = (idx & 15) << 2;
        float4 v = *(const float4*)(Q + (brow + qt * 64 + row) * Dv + hcol + c4);
        *(float4*)(Qs + row * ATT_PAD + c4) = v;
    }

    float m_run[4], l_run[4], o[4][4];
#pragma unroll
    for (int rr = 0; rr < 4; rr++) {
        m_run[rr] = -1e30f;
        l_run[rr] = 0.f;
#pragma unroll
        for (int cc = 0; cc < 4; cc++) o[rr][cc] = 0.f;
    }

    for (int kt = 0; kt < Sv / 64; kt++) {
        __syncthreads();
#pragma unroll
        for (int i = 0; i < 4; i++) {
            int idx = tid + i * 256;
            int row = idx >> 4, c4 = (idx & 15) << 2;
            size_t grow = (brow + kt * 64 + row) * Dv + hcol + c4;
            *(float4*)(Ks + row * ATT_PAD + c4) = *(const float4*)(K + grow);
            *(float4*)(Vs + row * ATT_PAD + c4) = *(const float4*)(V + grow);
        }
        float mk[4];
#pragma unroll
        for (int cc = 0; cc < 4; cc++)
            mk[cc] = mask[b * Sv + kt * 64 + tx * 4 + cc] * -1e9f;
        __syncthreads();

        // S = Q @ K^T (64x64), each thread 4x4
        float s[4][4];
#pragma unroll
        for (int rr = 0; rr < 4; rr++)
#pragma unroll
            for (int cc = 0; cc < 4; cc++) s[rr][cc] = 0.f;

        for (int d = 0; d < 64; d += 4) {
            float4 q4[4], k4[4];
#pragma unroll
            for (int rr = 0; rr < 4; rr++)
                q4[rr] = *(float4*)(Qs + (ty * 4 + rr) * ATT_PAD + d);
#pragma unroll
            for (int cc = 0; cc < 4; cc++)
                k4[cc] = *(float4*)(Ks + (tx * 4 + cc) * ATT_PAD + d);
#pragma unroll
            for (int rr = 0; rr < 4; rr++)
#pragma unroll
                for (int cc = 0; cc < 4; cc++)
                    s[rr][cc] += q4[rr].x * k4[cc].x + q4[rr].y * k4[cc].y +
                                 q4[rr].z * k4[cc].z + q4[rr].w * k4[cc].w;
        }

        // online softmax over the 64 keys of this tile
#pragma unroll
        for (int rr = 0; rr < 4; rr++) {
            float tm = -1e30f;
#pragma unroll
            for (int cc = 0; cc < 4; cc++) {
                s[rr][cc] = s[rr][cc] * 0.125f + mk[cc];
                tm = fmaxf(tm, s[rr][cc]);
            }
#pragma unroll
            for (int msk = 8; msk; msk >>= 1)
                tm = fmaxf(tm, __shfl_xor_sync(0xffffffffu, tm, msk));
            float mnew  = fmaxf(m_run[rr], tm);
            float alpha = __expf(m_run[rr] - mnew);
            m_run[rr]   = mnew;
            float ps = 0.f;
#pragma unroll
            for (int cc = 0; cc < 4; cc++) {
                float p = __expf(s[rr][cc] - mnew);
                s[rr][cc] = p;
                ps += p;
            }
#pragma unroll
            for (int msk = 8; msk; msk >>= 1)
                ps += __shfl_xor_sync(0xffffffffu, ps, msk);
            l_run[rr] = l_run[rr] * alpha + ps;
#pragma unroll
            for (int cc = 0; cc < 4; cc++) o[rr][cc] *= alpha;
        }

        // stage P to smem
#pragma unroll
        for (int rr = 0; rr < 4; rr++) {
            float4 pv = make_float4(s[rr][0], s[rr][1], s[rr][2], s[rr][3]);
            *(float4*)(Ps + (ty * 4 + rr) * ATT_PAD + tx * 4) = pv;
        }
        __syncthreads();

        // O += P @ V  (64x64x64)
        for (int j = 0; j < 64; j += 4) {
            float4 p4[4], v4[4];
#pragma unroll
            for (int rr = 0; rr < 4; rr++)
                p4[rr] = *(float4*)(Ps + (ty * 4 + rr) * ATT_PAD + j);
#pragma unroll
            for (int jj = 0; jj < 4; jj++)
                v4[jj] = *(float4*)(Vs + (j + jj) * ATT_PAD + tx * 4);
#pragma unroll
            for (int rr = 0; rr < 4; rr++) {
                o[rr][0] += p4[rr].x * v4[0].x + p4[rr].y * v4[1].x +
                            p4[rr].z * v4[2].x + p4[rr].w * v4[3].x;
                o[rr][1] += p4[rr].x * v4[0].y + p4[rr].y * v4[1].y +
                            p4[rr].z * v4[2].y + p4[rr].w * v4[3].y;
                o[rr][2] += p4[rr].x * v4[0].z + p4[rr].y * v4[1].z +
                            p4[rr].z * v4[2].z + p4[rr].w * v4[3].z;
                o[rr][3] += p4[rr].x * v4[0].w + p4[rr].y * v4[1].w +
                            p4[rr].z * v4[2].w + p4[rr].w * v4[3].w;
            }
        }
    }

    // write normalized output
#pragma unroll
    for (int rr = 0; rr < 4; rr++) {
        float inv = 1.f / l_run[rr];
        float4 v = make_float4(o[rr][0] * inv, o[rr][1] * inv,
                               o[rr][2] * inv, o[rr][3] * inv);
        *(float4*)(O + (brow + qt * 64 + ty * 4 + rr) * Dv + hcol + tx * 4) = v;
    }
}

// ---------------------------------------------------------------------------
// LayerNorm over full [S,D] slab (per batch): residual add + partial sums.
// grid = (128, B), 256 threads, 4096 elements per block.
// ---------------------------------------------------------------------------
__global__ __launch_bounds__(256) void ln_reduce(
    const float* __restrict__ X, const float* __restrict__ Y,
    float* __restrict__ R, float* __restrict__ part)
{
    const int b   = blockIdx.y;
    const int blk = blockIdx.x;
    const int tid = threadIdx.x;
    const size_t base = (size_t)b * SDv + (size_t)blk * 4096;

    float s = 0.f, s2 = 0.f;
#pragma unroll
    for (int i = 0; i < 4; i++) {
        size_t off = base + (size_t)(tid + i * 256) * 4;
        float4 x4 = *(const float4*)(X + off);
        float4 y4 = *(const float4*)(Y + off);
        float4 r;
        r.x = x4.x + y4.x; r.y = x4.y + y4.y;
        r.z = x4.z + y4.z; r.w = x4.w + y4.w;
        *(float4*)(R + off) = r;
        s  += r.x + r.y + r.z + r.w;
        s2 += r.x * r.x + r.y * r.y + r.z * r.z + r.w * r.w;
    }

    __shared__ float rs[256], rs2[256];
    rs[tid] = s; rs2[tid] = s2;
    __syncthreads();
    for (int off = 128; off > 0; off >>= 1) {
        if (tid < off) { rs[tid] += rs[tid + off]; rs2[tid] += rs2[tid + off]; }
        __syncthreads();
    }
    if (tid == 0) {
        part[(b * 128 + blk) * 2 + 0] = rs[0];
        part[(b * 128 + blk) * 2 + 1] = rs2[0];
    }
}

__global__ __launch_bounds__(128) void ln_finalize(
    const float* __restrict__ part, float* __restrict__ stats)
{
    const int b = blockIdx.x;
    const int tid = threadIdx.x;
    float s  = part[(b * 128 + tid) * 2 + 0];
    float s2 = part[(b * 128 + tid) * 2 + 1];
    __shared__ float rs[128], rs2[128];
    rs[tid] = s; rs2[tid] = s2;
    __syncthreads();
    for (int off = 64; off > 0; off >>= 1) {
        if (tid < off) { rs[tid] += rs[tid + off]; rs2[tid] += rs2[tid + off]; }
        __syncthreads();
    }
    if (tid == 0) {
        float n = (float)SDv;
        float mean = rs[0] / n;
        float var  = rs2[0] / n - mean * mean;
        stats[b * 2 + 0] = mean;
        stats[b * 2 + 1] = rsqrtf(var + 1e-5f);
    }
}

__global__ __launch_bounds__(256) void ln_apply(
    const float* __restrict__ R, const float* __restrict__ stats,
    const float* __restrict__ W, const float* __restrict__ Bb,
    float* __restrict__ out)
{
    size_t i4 = (size_t)blockIdx.x * 256 + threadIdx.x;   // float4 index
    size_t e  = i4 * 4;
    int b  = (int)(e >> 19);           // S*D = 2^19
    int sd = (int)(e & (SDv - 1));
    float mean = stats[b * 2 + 0];
    float rstd = stats[b * 2 + 1];
    float4 r  = *(const float4*)(R + e);
    float4 w4 = *(const float4*)(W + sd);
    float4 b4 = *(const float4*)(Bb + sd);
    float4 y;
    y.x = (r.x - mean) * rstd * w4.x + b4.x;
    y.y = (r.y - mean) * rstd * w4.y + b4.y;
    y.z = (r.z - mean) * rstd * w4.z + b4.z;
    y.w = (r.w - mean) * rstd * w4.w + b4.w;
    *(float4*)(out + e) = y;
}

// ---------------------------------------------------------------------------
extern "C" void kernel_launch(void* const* d_in, const int* in_sizes, int n_in,
                              void* d_out, int out_size)
{
    const float* x     = (const float*)d_in[0];
    const float* mask  = (const float*)d_in[1];
    const float* wq    = (const float*)d_in[2];
    const float* bq    = (const float*)d_in[3];
    const float* wk    = (const float*)d_in[4];
    const float* bk    = (const float*)d_in[5];
    const float* wv    = (const float*)d_in[6];
    const float* bv    = (const float*)d_in[7];
    const float* wo    = (const float*)d_in[8];
    const float* bo    = (const float*)d_in[9];
    const float* w1    = (const float*)d_in[10];
    const float* b1    = (const float*)d_in[11];
    const float* w2    = (const float*)d_in[12];
    const float* b2    = (const float*)d_in[13];
    const float* ln1w  = (const float*)d_in[14];
    const float* ln1b  = (const float*)d_in[15];
    const float* ln2w  = (const float*)d_in[16];
    const float* ln2b  = (const float*)d_in[17];
    float* out = (float*)d_out;

    void* p;
    cudaGetSymbolAddress(&p, g_q);        float* q      = (float*)p;
    cudaGetSymbolAddress(&p, g_k);        float* k      = (float*)p;
    cudaGetSymbolAddress(&p, g_v);        float* v      = (float*)p;
    cudaGetSymbolAddress(&p, g_ctx);      float* ctx    = (float*)p;
    cudaGetSymbolAddress(&p, g_attnout);  float* attnO  = (float*)p;
    cudaGetSymbolAddress(&p, g_res1);     float* res1   = (float*)p;
    cudaGetSymbolAddress(&p, g_out1);     float* out1   = (float*)p;
    cudaGetSymbolAddress(&p, g_ffn);      float* ffn    = (float*)p;
    cudaGetSymbolAddress(&p, g_ffnout);   float* ffnO   = (float*)p;
    cudaGetSymbolAddress(&p, g_res2);     float* res2   = (float*)p;
    cudaGetSymbolAddress(&p, g_part1);    float* part1  = (float*)p;
    cudaGetSymbolAddress(&p, g_part2);    float* part2  = (float*)p;
    cudaGetSymbolAddress(&p, g_stats1);   float* stats1 = (float*)p;
    cudaGetSymbolAddress(&p, g_stats2);   float* stats2 = (float*)p;

    cudaFuncSetAttribute(attn_kernel,
                         cudaFuncAttributeMaxDynamicSharedMemorySize, ATT_SMEM);

    dim3 blk(256);
    dim3 gD(Dv / 128, BSv / 128);      // (4, 128)  N=512 GEMMs
    dim3 gF(DFFv / 128, BSv / 128);    // (16, 128) N=2048 GEMM
    dim3 gAttn(Sv / 64, Bv * Hv);      // (16, 128)
    dim3 gLNr(128, Bv);
    int  gApply = (BSv * Dv / 4) / 256; // 8192

    // QKV projections
    sgemm_bias<0><<<gD, blk>>>(x, wq, bq, q, BSv, Dv, Dv);
    sgemm_bias<0><<<gD, blk>>>(x, wk, bk, k, BSv, Dv, Dv);
    sgemm_bias<0><<<gD, blk>>>(x, wv, bv, v, BSv, Dv, Dv);

    // attention
    attn_kernel<<<gAttn, blk, ATT_SMEM>>>(q, k, v, mask, ctx);

    // output projection
    sgemm_bias<0><<<gD, blk>>>(ctx, wo, bo, attnO, BSv, Dv, Dv);

    // LN1 over residual
    ln_reduce<<<gLNr, blk>>>(x, attnO, res1, part1);
    ln_finalize<<<Bv, 128>>>(part1, stats1);
    ln_apply<<<gApply, blk>>>(res1, stats1, ln1w, ln1b, out1);

    // FFN
    sgemm_bias<1><<<gF, blk>>>(out1, w1, b1, ffn, BSv, DFFv, Dv);
    sgemm_bias<0><<<gD, blk>>>(ffn, w2, b2, ffnO, BSv, Dv, DFFv);

    // LN2 over residual -> final output
    ln_reduce<<<gLNr, blk>>>(out1, ffnO, res2, part2);
    ln_finalize<<<Bv, 128>>>(part2, stats2);
    ln_apply<<<gApply, blk>>>(res2, stats2, ln2w, ln2b, out);
}

// round 3
// speedup vs baseline: 2.6975x; 2.6975x over previous
#include <cuda_runtime.h>
#include <cstdint>
#include <math.h>

// Problem constants
static const int Bv   = 16;
static const int Sv   = 1024;
static const int Dv   = 512;
static const int DFFv = 2048;
static const int BSv  = Bv * Sv;        // 16384
static const int SDv  = Sv * Dv;        // 524288 = 2^19

// ---------------- scratch (device globals; no allocation allowed) ----------
__device__ float g_xr[BSv * Dv];          // tf32-rounded copy of x
__device__ float g_q[BSv * Dv];
__device__ float g_k[BSv * Dv];
__device__ float g_v[BSv * Dv];
__device__ float g_ctx[BSv * Dv];
__device__ float g_attnout[BSv * Dv];
__device__ float g_res1[BSv * Dv];
__device__ float g_out1[BSv * Dv];
__device__ float g_ffn[BSv * DFFv];
__device__ float g_ffnout[BSv * Dv];
__device__ float g_res2[BSv * Dv];
// tf32-rounded weight copies (native [K,N] layout)
__device__ float g_wqr[Dv * Dv];
__device__ float g_wkr[Dv * Dv];
__device__ float g_wvr[Dv * Dv];
__device__ float g_wor[Dv * Dv];
__device__ float g_w1r[Dv * DFFv];
__device__ float g_w2r[DFFv * Dv];
__device__ float g_part1[16 * 128 * 2];
__device__ float g_part2[16 * 128 * 2];
__device__ float g_stats1[16 * 2];
__device__ float g_stats2[16 * 2];

// ---------------------------------------------------------------------------
// helpers
// ---------------------------------------------------------------------------
__device__ __forceinline__ float rtf32(float x) {
    uint32_t r;
    asm("cvt.rna.tf32.f32 %0, %1;" : "=r"(r) : "f"(x));
    return __uint_as_float(r);
}
__device__ __forceinline__ uint32_t fu(float x) { return __float_as_uint(x); }

// m16n8k8 tf32 MMA, fp32 accumulate. A row-major, B "col" (fragment = B[k][n]).
__device__ __forceinline__ void mma8(float& d0, float& d1, float& d2, float& d3,
                                     uint32_t a0, uint32_t a1, uint32_t a2, uint32_t a3,
                                     uint32_t b0, uint32_t b1) {
    asm volatile(
        "mma.sync.aligned.m16n8k8.row.col.f32.tf32.tf32.f32 "
        "{%0,%1,%2,%3}, {%4,%5,%6,%7}, {%8,%9}, {%0,%1,%2,%3};"
        : "+f"(d0), "+f"(d1), "+f"(d2), "+f"(d3)
        : "r"(a0), "r"(a1), "r"(a2), "r"(a3), "r"(b0), "r"(b1));
}

// ---------------------------------------------------------------------------
// tf32 tensor-core GEMM: C[M,N] = A[M,K] @ B[K,N] + bias
// CTA 128x128, BK=16, 256 threads (8 warps: 4 in M x 2 in N, warp tile 32x64).
// Inputs must already be tf32-rounded. RELU/ROUND applied in epilogue.
// ---------------------------------------------------------------------------
template <int RELU, int ROUND>
__global__ void __launch_bounds__(256) gemm_mma(
    const float* __restrict__ A, const float* __restrict__ B,
    const float* __restrict__ bias, float* __restrict__ C,
    int N, int K)
{
    __shared__ float As[16][136];   // transposed: As[k][m], pad for frag LDS
    __shared__ float Bs[16][136];   // Bs[k][n]

    const int tid = threadIdx.x;
    const int lane = tid & 31, wid = tid >> 5;
    const int qid = lane >> 2, tg = lane & 3;
    const int wm = (wid & 3) * 32;          // warp row base within tile
    const int wn = (wid >> 2) * 64;         // warp col base within tile
    const int m0 = blockIdx.y * 128, n0 = blockIdx.x * 128;

    float acc[2][8][4];
#pragma unroll
    for (int mt = 0; mt < 2; mt++)
#pragma unroll
        for (int nt = 0; nt < 8; nt++)
#pragma unroll
            for (int r = 0; r < 4; r++) acc[mt][nt][r] = 0.f;

    float4 pa[2], pb[2];
    // prologue (k0 = 0)
#pragma unroll
    for (int i = 0; i < 2; i++) {
        int idx = tid + i * 256;
        int row = idx >> 2, q4 = (idx & 3) << 2;
        pa[i] = *(const float4*)(A + (size_t)(m0 + row) * K + q4);
    }
#pragma unroll
    for (int i = 0; i < 2; i++) {
        int idx = tid + i * 256;
        int row = idx >> 5, c = (idx & 31) << 2;
        pb[i] = *(const float4*)(B + (size_t)row * N + n0 + c);
    }

    for (int k0 = 0; k0 < K; k0 += 16) {
        __syncthreads();
#pragma unroll
        for (int i = 0; i < 2; i++) {
            int idx = tid + i * 256;
            int row = idx >> 2, q4 = (idx & 3) << 2;
            As[q4 + 0][row] = pa[i].x;
            As[q4 + 1][row] = pa[i].y;
            As[q4 + 2][row] = pa[i].z;
            As[q4 + 3][row] = pa[i].w;
        }
#pragma unroll
        for (int i = 0; i < 2; i++) {
            int idx = tid + i * 256;
            int row = idx >> 5, c = (idx & 31) << 2;
            *(float4*)&Bs[row][c] = pb[i];
        }
        __syncthreads();

        if (k0 + 16 < K) {
            int kn = k0 + 16;
#pragma unroll
            for (int i = 0; i < 2; i++) {
                int idx = tid + i * 256;
                int row = idx >> 2, q4 = (idx & 3) << 2;
                pa[i] = *(const float4*)(A + (size_t)(m0 + row) * K + kn + q4);
            }
#pragma unroll
            for (int i = 0; i < 2; i++) {
                int idx = tid + i * 256;
                int row = idx >> 5, c = (idx & 31) << 2;
                pb[i] = *(const float4*)(B + (size_t)(kn + row) * N + n0 + c);
            }
        }

#pragma unroll
        for (int ko = 0; ko < 16; ko += 8) {
            uint32_t af[2][4];
#pragma unroll
            for (int mt = 0; mt < 2; mt++) {
                int rm = wm + mt * 16 + qid;
                af[mt][0] = fu(As[ko + tg][rm]);
                af[mt][1] = fu(As[ko + tg][rm + 8]);
                af[mt][2] = fu(As[ko + tg + 4][rm]);
                af[mt][3] = fu(As[ko + tg + 4][rm + 8]);
            }
#pragma unroll
            for (int nt = 0; nt < 8; nt++) {
                int cn = wn + nt * 8 + qid;
                uint32_t b0 = fu(Bs[ko + tg][cn]);
                uint32_t b1 = fu(Bs[ko + tg + 4][cn]);
                mma8(acc[0][nt][0], acc[0][nt][1], acc[0][nt][2], acc[0][nt][3],
                     af[0][0], af[0][1], af[0][2], af[0][3], b0, b1);
                mma8(acc[1][nt][0], acc[1][nt][1], acc[1][nt][2], acc[1][nt][3],
                     af[1][0], af[1][1], af[1][2], af[1][3], b0, b1);
            }
        }
    }

    // epilogue
#pragma unroll
    for (int mt = 0; mt < 2; mt++) {
        int r_lo = m0 + wm + mt * 16 + qid;
        int r_hi = r_lo + 8;
#pragma unroll
        for (int nt = 0; nt < 8; nt++) {
            int col = n0 + wn + nt * 8 + 2 * tg;
            float bx = bias[col], by = bias[col + 1];
            float v0 = acc[mt][nt][0] + bx, v1 = acc[mt][nt][1] + by;
            float v2 = acc[mt][nt][2] + bx, v3 = acc[mt][nt][3] + by;
            if (RELU) {
                v0 = fmaxf(v0, 0.f); v1 = fmaxf(v1, 0.f);
                v2 = fmaxf(v2, 0.f); v3 = fmaxf(v3, 0.f);
            }
            if (ROUND) {
                v0 = rtf32(v0); v1 = rtf32(v1); v2 = rtf32(v2); v3 = rtf32(v3);
            }
            *(float2*)(C + (size_t)r_lo * N + col) = make_float2(v0, v1);
            *(float2*)(C + (size_t)r_hi * N + col) = make_float2(v2, v3);
        }
    }
}

// tf32-round copy (element count multiple of 1024)
__global__ void __launch_bounds__(256) round_copy(const float* __restrict__ src,
                                                  float* __restrict__ dst)
{
    size_t i = ((size_t)blockIdx.x * 256 + threadIdx.x) * 4;
    float4 v = *(const float4*)(src + i);
    v.x = rtf32(v.x); v.y = rtf32(v.y); v.z = rtf32(v.z); v.w = rtf32(v.w);
    *(float4*)(dst + i) = v;
}

// ---------------------------------------------------------------------------
// Flash attention with tf32 MMAs.
// grid = (S/64, B*H), block = 128 (4 warps). Each warp owns 16 query rows.
// Q,K,V pre-rounded to tf32. Output rounded (feeds O-proj GEMM).
// ---------------------------------------------------------------------------
#define APAD 72
#define ATT_SMEM ((3 * 64 * APAD + 1024) * 4)   // Ks,Vs,Ps + mask row

__global__ void __launch_bounds__(128) attn_mma(
    const float* __restrict__ Q, const float* __restrict__ K,
    const float* __restrict__ V, const float* __restrict__ mask,
    float* __restrict__ O)
{
    extern __shared__ float sm[];
    float (*Ks)[APAD] = (float(*)[APAD])(sm);
    float (*Vs)[APAD] = (float(*)[APAD])(sm + 64 * APAD);
    float (*Ps)[APAD] = (float(*)[APAD])(sm + 2 * 64 * APAD);  // also Q staging
    float* Msk = sm + 3 * 64 * APAD;

    const int tid = threadIdx.x;
    const int lane = tid & 31, wid = tid >> 5;
    const int qid = lane >> 2, tg = lane & 3;
    const int qt = blockIdx.x;
    const int b  = blockIdx.y >> 3;
    const int h  = blockIdx.y & 7;
    const size_t hcol = (size_t)h * 64;
    const size_t brow = (size_t)b * Sv;

    // mask row (pre-scaled by -1e9)
#pragma unroll
    for (int i = 0; i < 8; i++)
        Msk[tid + i * 128] = mask[b * Sv + tid + i * 128] * -1e9f;

    // stage Q tile into Ps
#pragma unroll
    for (int i = 0; i < 8; i++) {
        int idx = tid + i * 128;
        int row = idx >> 4, c4 = (idx & 15) << 2;
        *(float4*)(&Ps[row][c4]) =
            *(const float4*)(Q + (brow + qt * 64 + row) * Dv + hcol + c4);
    }
    __syncthreads();

    // Q fragments: 8 k-steps x 4 regs (warp's 16 rows)
    uint32_t qf[8][4];
    {
        int rm = wid * 16 + qid;
#pragma unroll
        for (int kk = 0; kk < 8; kk++) {
            qf[kk][0] = fu(Ps[rm][kk * 8 + tg]);
            qf[kk][1] = fu(Ps[rm + 8][kk * 8 + tg]);
            qf[kk][2] = fu(Ps[rm][kk * 8 + tg + 4]);
            qf[kk][3] = fu(Ps[rm + 8][kk * 8 + tg + 4]);
        }
    }

    float m_lo = -1e30f, m_hi = -1e30f, l_lo = 0.f, l_hi = 0.f;
    float of[8][4];
#pragma unroll
    for (int nt = 0; nt < 8; nt++)
#pragma unroll
        for (int r = 0; r < 4; r++) of[nt][r] = 0.f;

    for (int kt = 0; kt < Sv / 64; kt++) {
        __syncthreads();
#pragma unroll
        for (int i = 0; i < 8; i++) {
            int idx = tid + i * 128;
            int row = idx >> 4, c4 = (idx & 15) << 2;
            size_t g = (brow + kt * 64 + row) * Dv + hcol + c4;
            *(float4*)(&Ks[row][c4]) = *(const float4*)(K + g);
            *(float4*)(&Vs[row][c4]) = *(const float4*)(V + g);
        }
        __syncthreads();

        // S = Q @ K^T  (warp's 16 rows x 64 keys)
        float sc[8][4];
#pragma unroll
        for (int nt = 0; nt < 8; nt++) {
#pragma unroll
            for (int r = 0; r < 4; r++) sc[nt][r] = 0.f;
#pragma unroll
            for (int kk = 0; kk < 8; kk++) {
                uint32_t b0 = fu(Ks[nt * 8 + qid][kk * 8 + tg]);
                uint32_t b1 = fu(Ks[nt * 8 + qid][kk * 8 + tg + 4]);
                mma8(sc[nt][0], sc[nt][1], sc[nt][2], sc[nt][3],
                     qf[kk][0], qf[kk][1], qf[kk][2], qf[kk][3], b0, b1);
            }
        }

        // scale + mask, online softmax
        float tmax_lo = -1e30f, tmax_hi = -1e30f;
#pragma unroll
        for (int nt = 0; nt < 8; nt++) {
            int col = kt * 64 + nt * 8 + 2 * tg;
            float mk0 = Msk[col], mk1 = Msk[col + 1];
            sc[nt][0] = sc[nt][0] * 0.125f + mk0;
            sc[nt][1] = sc[nt][1] * 0.125f + mk1;
            sc[nt][2] = sc[nt][2] * 0.125f + mk0;
            sc[nt][3] = sc[nt][3] * 0.125f + mk1;
            tmax_lo = fmaxf(tmax_lo, fmaxf(sc[nt][0], sc[nt][1]));
            tmax_hi = fmaxf(tmax_hi, fmaxf(sc[nt][2], sc[nt][3]));
        }
        tmax_lo = fmaxf(tmax_lo, __shfl_xor_sync(0xffffffffu, tmax_lo, 1));
        tmax_lo = fmaxf(tmax_lo, __shfl_xor_sync(0xffffffffu, tmax_lo, 2));
        tmax_hi = fmaxf(tmax_hi, __shfl_xor_sync(0xffffffffu, tmax_hi, 1));
        tmax_hi = fmaxf(tmax_hi, __shfl_xor_sync(0xffffffffu, tmax_hi, 2));

        float mn_lo = fmaxf(m_lo, tmax_lo);
        float mn_hi = fmaxf(m_hi, tmax_hi);
        float al_lo = __expf(m_lo - mn_lo);
        float al_hi = __expf(m_hi - mn_hi);
        m_lo = mn_lo; m_hi = mn_hi;

        float ps_lo = 0.f, ps_hi = 0.f;
#pragma unroll
        for (int nt = 0; nt < 8; nt++) {
            sc[nt][0] = __expf(sc[nt][0] - mn_lo);
            sc[nt][1] = __expf(sc[nt][1] - mn_lo);
            sc[nt][2] = __expf(sc[nt][2] - mn_hi);
            sc[nt][3] = __expf(sc[nt][3] - mn_hi);
            ps_lo += sc[nt][0] + sc[nt][1];
            ps_hi += sc[nt][2] + sc[nt][3];
        }
        ps_lo += __shfl_xor_sync(0xffffffffu, ps_lo, 1);
        ps_lo += __shfl_xor_sync(0xffffffffu, ps_lo, 2);
        ps_hi += __shfl_xor_sync(0xffffffffu, ps_hi, 1);
        ps_hi += __shfl_xor_sync(0xffffffffu, ps_hi, 2);
        l_lo = l_lo * al_lo + ps_lo;
        l_hi = l_hi * al_hi + ps_hi;

        // rescale O, stage P (tf32-rounded) into warp-private Ps region
#pragma unroll
        for (int nt = 0; nt < 8; nt++) {
            of[nt][0] *= al_lo; of[nt][1] *= al_lo;
            of[nt][2] *= al_hi; of[nt][3] *= al_hi;
            int pr = wid * 16 + qid;
            int pc = nt * 8 + 2 * tg;
            *(float2*)(&Ps[pr][pc])     = make_float2(rtf32(sc[nt][0]), rtf32(sc[nt][1]));
            *(float2*)(&Ps[pr + 8][pc]) = make_float2(rtf32(sc[nt][2]), rtf32(sc[nt][3]));
        }
        __syncwarp();

        // O += P @ V
#pragma unroll
        for (int kk = 0; kk < 8; kk++) {
            int rm = wid * 16 + qid;
            uint32_t pa0 = fu(Ps[rm][kk * 8 + tg]);
            uint32_t pa1 = fu(Ps[rm + 8][kk * 8 + tg]);
            uint32_t pa2 = fu(Ps[rm][kk * 8 + tg + 4]);
            uint32_t pa3 = fu(Ps[rm + 8][kk * 8 + tg + 4]);
#pragma unroll
            for (int nt = 0; nt < 8; nt++) {
                uint32_t b0 = fu(Vs[kk * 8 + tg][nt * 8 + qid]);
                uint32_t b1 = fu(Vs[kk * 8 + tg + 4][nt * 8 + qid]);
                mma8(of[nt][0], of[nt][1], of[nt][2], of[nt][3],
                     pa0, pa1, pa2, pa3, b0, b1);
            }
        }
        __syncwarp();
    }

    // write normalized, tf32-rounded output (feeds O-projection)
    float inv_lo = 1.f / l_lo, inv_hi = 1.f / l_hi;
    size_t r_lo = brow + qt * 64 + wid * 16 + qid;
    size_t r_hi = r_lo + 8;
#pragma unroll
    for (int nt = 0; nt < 8; nt++) {
        size_t col = hcol + nt * 8 + 2 * tg;
        *(float2*)(O + r_lo * Dv + col) =
            make_float2(rtf32(of[nt][0] * inv_lo), rtf32(of[nt][1] * inv_lo));
        *(float2*)(O + r_hi * Dv + col) =
            make_float2(rtf32(of[nt][2] * inv_hi), rtf32(of[nt][3] * inv_hi));
    }
}

// ---------------------------------------------------------------------------
// LayerNorm over full [S,D] slab (per batch)
// ---------------------------------------------------------------------------
__global__ void __launch_bounds__(256) ln_reduce(
    const float* __restrict__ X, const float* __restrict__ Y,
    float* __restrict__ R, float* __restrict__ part)
{
    const int b   = blockIdx.y;
    const int blk = blockIdx.x;
    const int tid = threadIdx.x;
    const size_t base = (size_t)b * SDv + (size_t)blk * 4096;

    float s = 0.f, s2 = 0.f;
#pragma unroll
    for (int i = 0; i < 4; i++) {
        size_t off = base + (size_t)(tid + i * 256) * 4;
        float4 x4 = *(const float4*)(X + off);
        float4 y4 = *(const float4*)(Y + off);
        float4 r;
        r.x = x4.x + y4.x; r.y = x4.y + y4.y;
        r.z = x4.z + y4.z; r.w = x4.w + y4.w;
        *(float4*)(R + off) = r;
        s  += r.x + r.y + r.z + r.w;
        s2 += r.x * r.x + r.y * r.y + r.z * r.z + r.w * r.w;
    }

    __shared__ float rs[256], rs2[256];
    rs[tid] = s; rs2[tid] = s2;
    __syncthreads();
    for (int off = 128; off > 0; off >>= 1) {
        if (tid < off) { rs[tid] += rs[tid + off]; rs2[tid] += rs2[tid + off]; }
        __syncthreads();
    }
    if (tid == 0) {
        part[(b * 128 + blk) * 2 + 0] = rs[0];
        part[(b * 128 + blk) * 2 + 1] = rs2[0];
    }
}

__global__ void __launch_bounds__(128) ln_finalize(
    const float* __restrict__ part, float* __restrict__ stats)
{
    const int b = blockIdx.x;
    const int tid = threadIdx.x;
    float s  = part[(b * 128 + tid) * 2 + 0];
    float s2 = part[(b * 128 + tid) * 2 + 1];
    __shared__ float rs[128], rs2[128];
    rs[tid] = s; rs2[tid] = s2;
    __syncthreads();
    for (int off = 64; off > 0; off >>= 1) {
        if (tid < off) { rs[tid] += rs[tid + off]; rs2[tid] += rs2[tid + off]; }
        __syncthreads();
    }
    if (tid == 0) {
        float n = (float)SDv;
        float mean = rs[0] / n;
        float var  = rs2[0] / n - mean * mean;
        stats[b * 2 + 0] = mean;
        stats[b * 2 + 1] = rsqrtf(var + 1e-5f);
    }
}

template <int ROUND>
__global__ void __launch_bounds__(256) ln_apply(
    const float* __restrict__ R, const float* __restrict__ stats,
    const float* __restrict__ W, const float* __restrict__ Bb,
    float* __restrict__ out)
{
    size_t i4 = (size_t)blockIdx.x * 256 + threadIdx.x;
    size_t e  = i4 * 4;
    int b  = (int)(e >> 19);
    int sd = (int)(e & (SDv - 1));
    float mean = stats[b * 2 + 0];
    float rstd = stats[b * 2 + 1];
    float4 r  = *(const float4*)(R + e);
    float4 w4 = *(const float4*)(W + sd);
    float4 b4 = *(const float4*)(Bb + sd);
    float4 y;
    y.x = (r.x - mean) * rstd * w4.x + b4.x;
    y.y = (r.y - mean) * rstd * w4.y + b4.y;
    y.z = (r.z - mean) * rstd * w4.z + b4.z;
    y.w = (r.w - mean) * rstd * w4.w + b4.w;
    if (ROUND) { y.x = rtf32(y.x); y.y = rtf32(y.y); y.z = rtf32(y.z); y.w = rtf32(y.w); }
    *(float4*)(out + e) = y;
}

// ---------------------------------------------------------------------------
extern "C" void kernel_launch(void* const* d_in, const int* in_sizes, int n_in,
                              void* d_out, int out_size)
{
    const float* x    = (const float*)d_in[0];
    const float* mask = (const float*)d_in[1];
    const float* wq   = (const float*)d_in[2];
    const float* bq   = (const float*)d_in[3];
    const float* wk   = (const float*)d_in[4];
    const float* bk   = (const float*)d_in[5];
    const float* wv   = (const float*)d_in[6];
    const float* bv   = (const float*)d_in[7];
    const float* wo   = (const float*)d_in[8];
    const float* bo   = (const float*)d_in[9];
    const float* w1   = (const float*)d_in[10];
    const float* b1   = (const float*)d_in[11];
    const float* w2   = (const float*)d_in[12];
    const float* b2   = (const float*)d_in[13];
    const float* ln1w = (const float*)d_in[14];
    const float* ln1b = (const float*)d_in[15];
    const float* ln2w = (const float*)d_in[16];
    const float* ln2b = (const float*)d_in[17];
    float* out = (float*)d_out;

    void* p;
    cudaGetSymbolAddress(&p, g_xr);      float* xr     = (float*)p;
    cudaGetSymbolAddress(&p, g_q);       float* q      = (float*)p;
    cudaGetSymbolAddress(&p, g_k);       float* k      = (float*)p;
    cudaGetSymbolAddress(&p, g_v);       float* v      = (float*)p;
    cudaGetSymbolAddress(&p, g_ctx);     float* ctx    = (float*)p;
    cudaGetSymbolAddress(&p, g_attnout); float* attnO  = (float*)p;
    cudaGetSymbolAddress(&p, g_res1);    float* res1   = (float*)p;
    cudaGetSymbolAddress(&p, g_out1);    float* out1   = (float*)p;
    cudaGetSymbolAddress(&p, g_ffn);     float* ffn    = (float*)p;
    cudaGetSymbolAddress(&p, g_ffnout);  float* ffnO   = (float*)p;
    cudaGetSymbolAddress(&p, g_res2);    float* res2   = (float*)p;
    cudaGetSymbolAddress(&p, g_wqr);     float* wqr    = (float*)p;
    cudaGetSymbolAddress(&p, g_wkr);     float* wkr    = (float*)p;
    cudaGetSymbolAddress(&p, g_wvr);     float* wvr    = (float*)p;
    cudaGetSymbolAddress(&p, g_wor);     float* wor    = (float*)p;
    cudaGetSymbolAddress(&p, g_w1r);     float* w1r    = (float*)p;
    cudaGetSymbolAddress(&p, g_w2r);     float* w2r    = (float*)p;
    cudaGetSymbolAddress(&p, g_part1);   float* part1  = (float*)p;
    cudaGetSymbolAddress(&p, g_part2);   float* part2  = (float*)p;
    cudaGetSymbolAddress(&p, g_stats1);  float* stats1 = (float*)p;
    cudaGetSymbolAddress(&p, g_stats2);  float* stats2 = (float*)p;

    cudaFuncSetAttribute(attn_mma,
                         cudaFuncAttributeMaxDynamicSharedMemorySize, ATT_SMEM);

    dim3 blk(256);
    dim3 gD(Dv / 128, BSv / 128);      // (4, 128)
    dim3 gF(DFFv / 128, BSv / 128);    // (16, 128)
    dim3 gAttn(Sv / 64, Bv * 8);       // (16, 128)
    dim3 gLNr(128, Bv);
    int  gApply = (BSv * Dv / 4) / 256;

    // pre-passes: tf32-round x and weights (native [K,N] layout)
    round_copy<<<(BSv * Dv / 4) / 256, 256>>>(x, xr);
    round_copy<<<(Dv * Dv / 4) / 256, 256>>>(wq, wqr);
    round_copy<<<(Dv * Dv / 4) / 256, 256>>>(wk, wkr);
    round_copy<<<(Dv * Dv / 4) / 256, 256>>>(wv, wvr);
    round_copy<<<(Dv * Dv / 4) / 256, 256>>>(wo, wor);
    round_copy<<<(Dv * DFFv / 4) / 256, 256>>>(w1, w1r);
    round_copy<<<(Dv * DFFv / 4) / 256, 256>>>(w2, w2r);

    // QKV projections (outputs rounded -> attention operands)
    gemm_mma<0, 1><<<gD, blk>>>(xr, wqr, bq, q, Dv, Dv);
    gemm_mma<0, 1><<<gD, blk>>>(xr, wkr, bk, k, Dv, Dv);
    gemm_mma<0, 1><<<gD, blk>>>(xr, wvr, bv, v, Dv, Dv);

    // attention (ctx rounded in epilogue)
    attn_mma<<<gAttn, 128, ATT_SMEM>>>(q, k, v, mask, ctx);

    // output projection (full fp32 out)
    gemm_mma<0, 0><<<gD, blk>>>(ctx, wor, bo, attnO, Dv, Dv);

    // LN1 (out1 rounded -> FFN1 operand)
    ln_reduce<<<gLNr, blk>>>(x, attnO, res1, part1);
    ln_finalize<<<Bv, 128>>>(part1, stats1);
    ln_apply<1><<<gApply, blk>>>(res1, stats1, ln1w, ln1b, out1);

    // FFN
    gemm_mma<1, 1><<<gF, blk>>>(out1, w1r, b1, ffn, DFFv, Dv);
    gemm_mma<0, 0><<<gD, blk>>>(ffn, w2r, b2, ffnO, Dv, DFFv);

    // LN2 -> final output
    ln_reduce<<<gLNr, blk>>>(out1, ffnO, res2, part2);
    ln_finalize<<<Bv, 128>>>(part2, stats2);
    ln_apply<0><<<gApply, blk>>>(res2, stats2, ln2w, ln2b, out);
}

// round 4
// speedup vs baseline: 6.1350x; 2.2743x over previous
#include <cuda_runtime.h>
#include <cuda_fp16.h>
#include <cstdint>
#include <math.h>

// Problem constants
static const int Bv   = 16;
static const int Sv   = 1024;
static const int Dv   = 512;
static const int DFFv = 2048;
static const int BSv  = Bv * Sv;        // 16384
static const int SDv  = Sv * Dv;        // 524288 = 2^19

// ---------------- scratch (device globals; no allocation allowed) ----------
__device__ __half g_xh[BSv * Dv];
__device__ __half g_qh[BSv * Dv];
__device__ __half g_kh[BSv * Dv];
__device__ __half g_vh[BSv * Dv];
__device__ __half g_ctxh[BSv * Dv];
__device__ __half g_o1h[BSv * Dv];
__device__ __half g_ffnh[BSv * DFFv];
__device__ __half g_wqh[Dv * Dv];
__device__ __half g_wkh[Dv * Dv];
__device__ __half g_wvh[Dv * Dv];
__device__ __half g_woh[Dv * Dv];
__device__ __half g_w1h[Dv * DFFv];
__device__ __half g_w2h[DFFv * Dv];
__device__ float g_attnout[BSv * Dv];
__device__ float g_res1[BSv * Dv];
__device__ float g_out1[BSv * Dv];
__device__ float g_ffnout[BSv * Dv];
__device__ float g_res2[BSv * Dv];
__device__ float g_part1[16 * 128 * 2];
__device__ float g_part2[16 * 128 * 2];
__device__ float g_stats1[16 * 2];
__device__ float g_stats2[16 * 2];

// ---------------------------------------------------------------------------
// helpers
// ---------------------------------------------------------------------------
__device__ __forceinline__ void cp16(uint32_t dst, const void* src) {
    asm volatile("cp.async.cg.shared.global [%0], [%1], 16;"
                 :: "r"(dst), "l"(src));
}
__device__ __forceinline__ void cp_commit() {
    asm volatile("cp.async.commit_group;");
}
__device__ __forceinline__ void ldm_x4(uint32_t& r0, uint32_t& r1,
                                       uint32_t& r2, uint32_t& r3, uint32_t a) {
    asm volatile("ldmatrix.sync.aligned.m8n8.x4.shared.b16 {%0,%1,%2,%3}, [%4];"
                 : "=r"(r0), "=r"(r1), "=r"(r2), "=r"(r3) : "r"(a));
}
__device__ __forceinline__ void ldm_x4t(uint32_t& r0, uint32_t& r1,
                                        uint32_t& r2, uint32_t& r3, uint32_t a) {
    asm volatile("ldmatrix.sync.aligned.m8n8.x4.trans.shared.b16 {%0,%1,%2,%3}, [%4];"
                 : "=r"(r0), "=r"(r1), "=r"(r2), "=r"(r3) : "r"(a));
}
// m16n8k16 fp16 MMA, fp32 accumulate
__device__ __forceinline__ void mma16(float* d, const uint32_t* a,
                                      uint32_t b0, uint32_t b1) {
    asm volatile(
        "mma.sync.aligned.m16n8k16.row.col.f32.f16.f16.f32 "
        "{%0,%1,%2,%3}, {%4,%5,%6,%7}, {%8,%9}, {%0,%1,%2,%3};"
        : "+f"(d[0]), "+f"(d[1]), "+f"(d[2]), "+f"(d[3])
        : "r"(a[0]), "r"(a[1]), "r"(a[2]), "r"(a[3]), "r"(b0), "r"(b1));
}
__device__ __forceinline__ uint32_t sptr(const void* p) {
    return (uint32_t)__cvta_generic_to_shared(p);
}

// ---------------------------------------------------------------------------
// fp16 tensor-core GEMM: C[M,N] = A[M,K] @ B[K,N] + bias
// CTA 128x128, BK=32, 256 threads (8 warps 4x2, warp tile 32x64),
// cp.async double-buffered.
// ---------------------------------------------------------------------------
template <int RELU, int HALF_OUT>
__global__ void __launch_bounds__(256) gemm_h(
    const __half* __restrict__ A, const __half* __restrict__ Bw,
    const float* __restrict__ bias, float* __restrict__ Cf,
    __half* __restrict__ Ch, int N, int K)
{
    __shared__ __align__(16) __half As[2][128][40];
    __shared__ __align__(16) __half Bs[2][32][136];

    const int tid = threadIdx.x;
    const int lane = tid & 31, wid = tid >> 5;
    const int qid = lane >> 2, tg = lane & 3;
    const int wm = (wid & 3) * 32, wn = (wid >> 2) * 64;
    const int m0 = blockIdx.y * 128, n0 = blockIdx.x * 128;

    float acc[2][8][4];
#pragma unroll
    for (int mt = 0; mt < 2; mt++)
#pragma unroll
        for (int nt = 0; nt < 8; nt++)
#pragma unroll
            for (int r = 0; r < 4; r++) acc[mt][nt][r] = 0.f;

    // ldmatrix lane addressing pieces
    const int lr = lane & 7;
    const int lmh = (lane >> 3) & 1;   // matrix low bit
    const int lkh = lane >> 4;         // matrix high bit

#define LOAD_STAGE(st, k0)                                                     \
    {                                                                          \
        _Pragma("unroll")                                                      \
        for (int i = 0; i < 2; i++) {                                          \
            int c = tid + i * 256;                                             \
            int row = c >> 2, seg = c & 3;                                     \
            cp16(sptr(&As[st][row][seg * 8]),                                  \
                 A + (size_t)(m0 + row) * K + (k0) + seg * 8);                 \
            int rb = c >> 4, sb = c & 15;                                      \
            cp16(sptr(&Bs[st][rb][sb * 8]),                                    \
                 Bw + (size_t)((k0) + rb) * N + n0 + sb * 8);                  \
        }                                                                      \
    }

    const int nk = K >> 5;
    LOAD_STAGE(0, 0);
    cp_commit();

    for (int it = 0; it < nk; it++) {
        const int st = it & 1;
        if (it + 1 < nk) {
            LOAD_STAGE(st ^ 1, (it + 1) * 32);
            cp_commit();
            asm volatile("cp.async.wait_group 1;");
        } else {
            asm volatile("cp.async.wait_group 0;");
        }
        __syncthreads();

#pragma unroll
        for (int ko2 = 0; ko2 < 2; ko2++) {
            const int ko = ko2 * 16;
            uint32_t af[2][4];
#pragma unroll
            for (int mt = 0; mt < 2; mt++) {
                int mrow = wm + mt * 16 + lmh * 8 + lr;
                ldm_x4(af[mt][0], af[mt][1], af[mt][2], af[mt][3],
                       sptr(&As[st][mrow][ko + lkh * 8]));
            }
#pragma unroll
            for (int p = 0; p < 4; p++) {
                uint32_t b0, b1, b2, b3;
                int krow = ko + lmh * 8 + lr;
                int ncol = wn + p * 16 + lkh * 8;
                ldm_x4t(b0, b1, b2, b3, sptr(&Bs[st][krow][ncol]));
                mma16(acc[0][2 * p],     af[0], b0, b1);
                mma16(acc[1][2 * p],     af[1], b0, b1);
                mma16(acc[0][2 * p + 1], af[0], b2, b3);
                mma16(acc[1][2 * p + 1], af[1], b2, b3);
            }
        }
        __syncthreads();
    }
#undef LOAD_STAGE

    // epilogue
#pragma unroll
    for (int mt = 0; mt < 2; mt++) {
        int r_lo = m0 + wm + mt * 16 + qid;
        int r_hi = r_lo + 8;
#pragma unroll
        for (int nt = 0; nt < 8; nt++) {
            int col = n0 + wn + nt * 8 + 2 * tg;
            float bx = bias[col], by = bias[col + 1];
            float v0 = acc[mt][nt][0] + bx, v1 = acc[mt][nt][1] + by;
            float v2 = acc[mt][nt][2] + bx, v3 = acc[mt][nt][3] + by;
            if (RELU) {
                v0 = fmaxf(v0, 0.f); v1 = fmaxf(v1, 0.f);
                v2 = fmaxf(v2, 0.f); v3 = fmaxf(v3, 0.f);
            }
            if (HALF_OUT) {
                *(__half2*)(Ch + (size_t)r_lo * N + col) = __floats2half2_rn(v0, v1);
                *(__half2*)(Ch + (size_t)r_hi * N + col) = __floats2half2_rn(v2, v3);
            } else {
                *(float2*)(Cf + (size_t)r_lo * N + col) = make_float2(v0, v1);
                *(float2*)(Cf + (size_t)r_hi * N + col) = make_float2(v2, v3);
            }
        }
    }
}

// float -> half conversion (n multiple of 1024)
__global__ void __launch_bounds__(256) f2h(const float* __restrict__ src,
                                           __half* __restrict__ dst)
{
    size_t i = ((size_t)blockIdx.x * 256 + threadIdx.x) * 4;
    float4 v = *(const float4*)(src + i);
    *(__half2*)(dst + i)     = __floats2half2_rn(v.x, v.y);
    *(__half2*)(dst + i + 2) = __floats2half2_rn(v.z, v.w);
}

// ---------------------------------------------------------------------------
// Flash attention, fp16 MMAs. grid = (S/64, B*H), block = 128 (4 warps).
// Each warp owns 16 query rows. K/V double-buffered via cp.async.
// smem layout (bytes): K[2]:0..18432, V[2]:18432..36864, P:36864..46080,
// mask:46080..50176
// ---------------------------------------------------------------------------
#define ATT_SMEM 50176

__global__ void __launch_bounds__(128) attn_h(
    const __half* __restrict__ Q, const __half* __restrict__ K,
    const __half* __restrict__ V, const float* __restrict__ mask,
    __half* __restrict__ O)
{
    extern __shared__ __align__(16) char smraw[];
    __half* KsB = (__half*)smraw;                  // [2][64][72]
    __half* VsB = (__half*)(smraw + 18432);        // [2][64][72]
    __half* Psb = (__half*)(smraw + 36864);        // [64][72]
    float*  Msk = (float*)(smraw + 46080);         // [1024]

    const int tid = threadIdx.x;
    const int lane = tid & 31, wid = tid >> 5;
    const int qid = lane >> 2, tg = lane & 3;
    const int lr = lane & 7, lmh = (lane >> 3) & 1, lkh = lane >> 4;
    const int qt = blockIdx.x;
    const int b  = blockIdx.y >> 3;
    const int h  = blockIdx.y & 7;
    const size_t hcol = (size_t)h * 64;
    const size_t brow = (size_t)b * Sv;

#define LOAD_KV(st, kt)                                                        \
    {                                                                          \
        _Pragma("unroll")                                                      \
        for (int i = 0; i < 4; i++) {                                          \
            int c = tid + i * 128;                                             \
            int row = c >> 3, seg = c & 7;                                     \
            size_t g = (brow + (kt) * 64 + row) * Dv + hcol + seg * 8;         \
            cp16(sptr(KsB + (st) * 4608 + row * 72 + seg * 8), K + g);         \
            cp16(sptr(VsB + (st) * 4608 + row * 72 + seg * 8), V + g);         \
        }                                                                      \
    }

    LOAD_KV(0, 0);
    cp_commit();

    // mask row (pre-scaled by -1e9)
#pragma unroll
    for (int i = 0; i < 8; i++)
        Msk[tid + i * 128] = mask[b * Sv + tid + i * 128] * -1e9f;

    // stage Q tile into P region
#pragma unroll
    for (int i = 0; i < 4; i++) {
        int c = tid + i * 128;
        int row = c >> 3, seg = c & 7;
        *(uint4*)(Psb + row * 72 + seg * 8) =
            *(const uint4*)(Q + (brow + qt * 64 + row) * Dv + hcol + seg * 8);
    }
    __syncthreads();

    // Q fragments: 4 k16-steps x 4 regs
    const int rm = wid * 16 + qid;
    uint32_t qf[4][4];
#pragma unroll
    for (int kk = 0; kk < 4; kk++) {
        qf[kk][0] = *(const uint32_t*)(Psb + rm * 72 + kk * 16 + 2 * tg);
        qf[kk][1] = *(const uint32_t*)(Psb + (rm + 8) * 72 + kk * 16 + 2 * tg);
        qf[kk][2] = *(const uint32_t*)(Psb + rm * 72 + kk * 16 + 2 * tg + 8);
        qf[kk][3] = *(const uint32_t*)(Psb + (rm + 8) * 72 + kk * 16 + 2 * tg + 8);
    }

    float m_lo = -1e30f, m_hi = -1e30f, l_lo = 0.f, l_hi = 0.f;
    float of[8][4];
#pragma unroll
    for (int nt = 0; nt < 8; nt++)
#pragma unroll
        for (int r = 0; r < 4; r++) of[nt][r] = 0.f;

    for (int kt = 0; kt < 16; kt++) {
        const int st = kt & 1;
        if (kt + 1 < 16) {
            LOAD_KV(st ^ 1, kt + 1);
            cp_commit();
            asm volatile("cp.async.wait_group 1;");
        } else {
            asm volatile("cp.async.wait_group 0;");
        }
        __syncthreads();

        // S = Q @ K^T
        float sc[8][4];
#pragma unroll
        for (int nt = 0; nt < 8; nt++) {
#pragma unroll
            for (int r = 0; r < 4; r++) sc[nt][r] = 0.f;
            const __half* kr = KsB + st * 4608 + (nt * 8 + qid) * 72;
#pragma unroll
            for (int kk = 0; kk < 4; kk++) {
                uint32_t b0 = *(const uint32_t*)(kr + kk * 16 + 2 * tg);
                uint32_t b1 = *(const uint32_t*)(kr + kk * 16 + 2 * tg + 8);
                mma16(sc[nt], qf[kk], b0, b1);
            }
        }

        // scale + mask, online softmax
        float tmax_lo = -1e30f, tmax_hi = -1e30f;
#pragma unroll
        for (int nt = 0; nt < 8; nt++) {
            int col = kt * 64 + nt * 8 + 2 * tg;
            float mk0 = Msk[col], mk1 = Msk[col + 1];
            sc[nt][0] = sc[nt][0] * 0.125f + mk0;
            sc[nt][1] = sc[nt][1] * 0.125f + mk1;
            sc[nt][2] = sc[nt][2] * 0.125f + mk0;
            sc[nt][3] = sc[nt][3] * 0.125f + mk1;
            tmax_lo = fmaxf(tmax_lo, fmaxf(sc[nt][0], sc[nt][1]));
            tmax_hi = fmaxf(tmax_hi, fmaxf(sc[nt][2], sc[nt][3]));
        }
        tmax_lo = fmaxf(tmax_lo, __shfl_xor_sync(0xffffffffu, tmax_lo, 1));
        tmax_lo = fmaxf(tmax_lo, __shfl_xor_sync(0xffffffffu, tmax_lo, 2));
        tmax_hi = fmaxf(tmax_hi, __shfl_xor_sync(0xffffffffu, tmax_hi, 1));
        tmax_hi = fmaxf(tmax_hi, __shfl_xor_sync(0xffffffffu, tmax_hi, 2));

        float mn_lo = fmaxf(m_lo, tmax_lo);
        float mn_hi = fmaxf(m_hi, tmax_hi);
        float al_lo = __expf(m_lo - mn_lo);
        float al_hi = __expf(m_hi - mn_hi);
        m_lo = mn_lo; m_hi = mn_hi;

        float ps_lo = 0.f, ps_hi = 0.f;
#pragma unroll
        for (int nt = 0; nt < 8; nt++) {
            sc[nt][0] = __expf(sc[nt][0] - mn_lo);
            sc[nt][1] = __expf(sc[nt][1] - mn_lo);
            sc[nt][2] = __expf(sc[nt][2] - mn_hi);
            sc[nt][3] = __expf(sc[nt][3] - mn_hi);
            ps_lo += sc[nt][0] + sc[nt][1];
            ps_hi += sc[nt][2] + sc[nt][3];
        }
        ps_lo += __shfl_xor_sync(0xffffffffu, ps_lo, 1);
        ps_lo += __shfl_xor_sync(0xffffffffu, ps_lo, 2);
        ps_hi += __shfl_xor_sync(0xffffffffu, ps_hi, 1);
        ps_hi += __shfl_xor_sync(0xffffffffu, ps_hi, 2);
        l_lo = l_lo * al_lo + ps_lo;
        l_hi = l_hi * al_hi + ps_hi;

        // rescale O, stage P as half (warp-private rows)
#pragma unroll
        for (int nt = 0; nt < 8; nt++) {
            of[nt][0] *= al_lo; of[nt][1] *= al_lo;
            of[nt][2] *= al_hi; of[nt][3] *= al_hi;
            *(__half2*)(Psb + rm * 72 + nt * 8 + 2 * tg) =
                __floats2half2_rn(sc[nt][0], sc[nt][1]);
            *(__half2*)(Psb + (rm + 8) * 72 + nt * 8 + 2 * tg) =
                __floats2half2_rn(sc[nt][2], sc[nt][3]);
        }
        __syncwarp();

        // O += P @ V
#pragma unroll
        for (int kk = 0; kk < 4; kk++) {
            uint32_t pa[4];
            pa[0] = *(const uint32_t*)(Psb + rm * 72 + kk * 16 + 2 * tg);
            pa[1] = *(const uint32_t*)(Psb + (rm + 8) * 72 + kk * 16 + 2 * tg);
            pa[2] = *(const uint32_t*)(Psb + rm * 72 + kk * 16 + 2 * tg + 8);
            pa[3] = *(const uint32_t*)(Psb + (rm + 8) * 72 + kk * 16 + 2 * tg + 8);
#pragma unroll
            for (int p = 0; p < 4; p++) {
                uint32_t b0, b1, b2, b3;
                int krow = kk * 16 + lmh * 8 + lr;
                int ncol = p * 16 + lkh * 8;
                ldm_x4t(b0, b1, b2, b3,
                        sptr(VsB + st * 4608 + krow * 72 + ncol));
                mma16(of[2 * p],     pa, b0, b1);
                mma16(of[2 * p + 1], pa, b2, b3);
            }
        }
        __syncthreads();
    }
#undef LOAD_KV

    // write normalized output as half (feeds O-projection)
    float inv_lo = 1.f / l_lo, inv_hi = 1.f / l_hi;
    size_t r_lo = brow + qt * 64 + rm;
    size_t r_hi = r_lo + 8;
#pragma unroll
    for (int nt = 0; nt < 8; nt++) {
        size_t col = hcol + nt * 8 + 2 * tg;
        *(__half2*)(O + r_lo * Dv + col) =
            __floats2half2_rn(of[nt][0] * inv_lo, of[nt][1] * inv_lo);
        *(__half2*)(O + r_hi * Dv + col) =
            __floats2half2_rn(of[nt][2] * inv_hi, of[nt][3] * inv_hi);
    }
}

// ---------------------------------------------------------------------------
// LayerNorm over full [S,D] slab (per batch)
// ---------------------------------------------------------------------------
__global__ void __launch_bounds__(256) ln_reduce(
    const float* __restrict__ X, const float* __restrict__ Y,
    float* __restrict__ R, float* __restrict__ part)
{
    const int b   = blockIdx.y;
    const int blk = blockIdx.x;
    const int tid = threadIdx.x;
    const size_t base = (size_t)b * SDv + (size_t)blk * 4096;

    float s = 0.f, s2 = 0.f;
#pragma unroll
    for (int i = 0; i < 4; i++) {
        size_t off = base + (size_t)(tid + i * 256) * 4;
        float4 x4 = *(const float4*)(X + off);
        float4 y4 = *(const float4*)(Y + off);
        float4 r;
        r.x = x4.x + y4.x; r.y = x4.y + y4.y;
        r.z = x4.z + y4.z; r.w = x4.w + y4.w;
        *(float4*)(R + off) = r;
        s  += r.x + r.y + r.z + r.w;
        s2 += r.x * r.x + r.y * r.y + r.z * r.z + r.w * r.w;
    }

    __shared__ float rs[256], rs2[256];
    rs[tid] = s; rs2[tid] = s2;
    __syncthreads();
    for (int off = 128; off > 0; off >>= 1) {
        if (tid < off) { rs[tid] += rs[tid + off]; rs2[tid] += rs2[tid + off]; }
        __syncthreads();
    }
    if (tid == 0) {
        part[(b * 128 + blk) * 2 + 0] = rs[0];
        part[(b * 128 + blk) * 2 + 1] = rs2[0];
    }
}

__global__ void __launch_bounds__(128) ln_finalize(
    const float* __restrict__ part, float* __restrict__ stats)
{
    const int b = blockIdx.x;
    const int tid = threadIdx.x;
    float s  = part[(b * 128 + tid) * 2 + 0];
    float s2 = part[(b * 128 + tid) * 2 + 1];
    __shared__ float rs[128], rs2[128];
    rs[tid] = s; rs2[tid] = s2;
    __syncthreads();
    for (int off = 64; off > 0; off >>= 1) {
        if (tid < off) { rs[tid] += rs[tid + off]; rs2[tid] += rs2[tid + off]; }
        __syncthreads();
    }
    if (tid == 0) {
        float n = (float)SDv;
        float mean = rs[0] / n;
        float var  = rs2[0] / n - mean * mean;
        stats[b * 2 + 0] = mean;
        stats[b * 2 + 1] = rsqrtf(var + 1e-5f);
    }
}

template <int HALF_COPY>
__global__ void __launch_bounds__(256) ln_apply(
    const float* __restrict__ R, const float* __restrict__ stats,
    const float* __restrict__ W, const float* __restrict__ Bb,
    float* __restrict__ out, __half* __restrict__ outh)
{
    size_t i4 = (size_t)blockIdx.x * 256 + threadIdx.x;
    size_t e  = i4 * 4;
    int b  = (int)(e >> 19);
    int sd = (int)(e & (SDv - 1));
    float mean = stats[b * 2 + 0];
    float rstd = stats[b * 2 + 1];
    float4 r  = *(const float4*)(R + e);
    float4 w4 = *(const float4*)(W + sd);
    float4 b4 = *(const float4*)(Bb + sd);
    float4 y;
    y.x = (r.x - mean) * rstd * w4.x + b4.x;
    y.y = (r.y - mean) * rstd * w4.y + b4.y;
    y.z = (r.z - mean) * rstd * w4.z + b4.z;
    y.w = (r.w - mean) * rstd * w4.w + b4.w;
    *(float4*)(out + e) = y;
    if (HALF_COPY) {
        *(__half2*)(outh + e)     = __floats2half2_rn(y.x, y.y);
        *(__half2*)(outh + e + 2) = __floats2half2_rn(y.z, y.w);
    }
}

// ---------------------------------------------------------------------------
extern "C" void kernel_launch(void* const* d_in, const int* in_sizes, int n_in,
                              void* d_out, int out_size)
{
    const float* x    = (const float*)d_in[0];
    const float* mask = (const float*)d_in[1];
    const float* wq   = (const float*)d_in[2];
    const float* bq   = (const float*)d_in[3];
    const float* wk   = (const float*)d_in[4];
    const float* bk   = (const float*)d_in[5];
    const float* wv   = (const float*)d_in[6];
    const float* bv   = (const float*)d_in[7];
    const float* wo   = (const float*)d_in[8];
    const float* bo   = (const float*)d_in[9];
    const float* w1   = (const float*)d_in[10];
    const float* b1   = (const float*)d_in[11];
    const float* w2   = (const float*)d_in[12];
    const float* b2   = (const float*)d_in[13];
    const float* ln1w = (const float*)d_in[14];
    const float* ln1b = (const float*)d_in[15];
    const float* ln2w = (const float*)d_in[16];
    const float* ln2b = (const float*)d_in[17];
    float* out = (float*)d_out;

    void* p;
    cudaGetSymbolAddress(&p, g_xh);      __half* xh    = (__half*)p;
    cudaGetSymbolAddress(&p, g_qh);      __half* qh    = (__half*)p;
    cudaGetSymbolAddress(&p, g_kh);      __half* kh    = (__half*)p;
    cudaGetSymbolAddress(&p, g_vh);      __half* vh    = (__half*)p;
    cudaGetSymbolAddress(&p, g_ctxh);    __half* ctxh  = (__half*)p;
    cudaGetSymbolAddress(&p, g_o1h);     __half* o1h   = (__half*)p;
    cudaGetSymbolAddress(&p, g_ffnh);    __half* ffnh  = (__half*)p;
    cudaGetSymbolAddress(&p, g_wqh);     __half* wqh   = (__half*)p;
    cudaGetSymbolAddress(&p, g_wkh);     __half* wkh   = (__half*)p;
    cudaGetSymbolAddress(&p, g_wvh);     __half* wvh   = (__half*)p;
    cudaGetSymbolAddress(&p, g_woh);     __half* woh   = (__half*)p;
    cudaGetSymbolAddress(&p, g_w1h);     __half* w1h   = (__half*)p;
    cudaGetSymbolAddress(&p, g_w2h);     __half* w2h   = (__half*)p;
    cudaGetSymbolAddress(&p, g_attnout); float* attnO  = (float*)p;
    cudaGetSymbolAddress(&p, g_res1);    float* res1   = (float*)p;
    cudaGetSymbolAddress(&p, g_out1);    float* out1   = (float*)p;
    cudaGetSymbolAddress(&p, g_ffnout);  float* ffnO   = (float*)p;
    cudaGetSymbolAddress(&p, g_res2);    float* res2   = (float*)p;
    cudaGetSymbolAddress(&p, g_part1);   float* part1  = (float*)p;
    cudaGetSymbolAddress(&p, g_part2);   float* part2  = (float*)p;
    cudaGetSymbolAddress(&p, g_stats1);  float* stats1 = (float*)p;
    cudaGetSymbolAddress(&p, g_stats2);  float* stats2 = (float*)p;

    cudaFuncSetAttribute(attn_h,
                         cudaFuncAttributeMaxDynamicSharedMemorySize, ATT_SMEM);

    dim3 blk(256);
    dim3 gD(Dv / 128, BSv / 128);      // (4, 128)
    dim3 gF(DFFv / 128, BSv / 128);    // (16, 128)
    dim3 gAttn(Sv / 64, Bv * 8);       // (16, 128)
    dim3 gLNr(128, Bv);
    int  gApply = (BSv * Dv / 4) / 256;

    // conversions to half
    f2h<<<(BSv * Dv) / 1024, 256>>>(x, xh);
    f2h<<<(Dv * Dv) / 1024, 256>>>(wq, wqh);
    f2h<<<(Dv * Dv) / 1024, 256>>>(wk, wkh);
    f2h<<<(Dv * Dv) / 1024, 256>>>(wv, wvh);
    f2h<<<(Dv * Dv) / 1024, 256>>>(wo, woh);
    f2h<<<(Dv * DFFv) / 1024, 256>>>(w1, w1h);
    f2h<<<(Dv * DFFv) / 1024, 256>>>(w2, w2h);

    // QKV projections (half outputs -> attention operands)
    gemm_h<0, 1><<<gD, blk>>>(xh, wqh, bq, nullptr, qh, Dv, Dv);
    gemm_h<0, 1><<<gD, blk>>>(xh, wkh, bk, nullptr, kh, Dv, Dv);
    gemm_h<0, 1><<<gD, blk>>>(xh, wvh, bv, nullptr, vh, Dv, Dv);

    // attention (half ctx out)
    attn_h<<<gAttn, 128, ATT_SMEM>>>(qh, kh, vh, mask, ctxh);

    // output projection (fp32 out for residual)
    gemm_h<0, 0><<<gD, blk>>>(ctxh, woh, bo, attnO, nullptr, Dv, Dv);

    // LN1 (out1 fp32 + half copy for FFN1)
    ln_reduce<<<gLNr, blk>>>(x, attnO, res1, part1);
    ln_finalize<<<Bv, 128>>>(part1, stats1);
    ln_apply<1><<<gApply, blk>>>(res1, stats1, ln1w, ln1b, out1, o1h);

    // FFN
    gemm_h<1, 1><<<gF, blk>>>(o1h, w1h, b1, nullptr, ffnh, DFFv, Dv);
    gemm_h<0, 0><<<gD, blk>>>(ffnh, w2h, b2, ffnO, nullptr, Dv, DFFv);

    // LN2 -> final output
    ln_reduce<<<gLNr, blk>>>(out1, ffnO, res2, part2);
    ln_finalize<<<Bv, 128>>>(part2, stats2);
    ln_apply<0><<<gApply, blk>>>(res2, stats2, ln2w, ln2b, out, nullptr);
}

// round 5
// speedup vs baseline: 6.2786x; 1.0234x over previous
#include <cuda_runtime.h>
#include <cuda_fp16.h>
#include <cstdint>
#include <math.h>

// Problem constants
static const int Bv   = 16;
static const int Sv   = 1024;
static const int Dv   = 512;
static const int DFFv = 2048;
static const int BSv  = Bv * Sv;        // 16384
static const int SDv  = Sv * Dv;        // 524288 = 2^19
static const int QS   = 1536;           // packed QKV row stride

// ---------------- scratch (device globals; no allocation allowed) ----------
__device__ __half g_xh[BSv * Dv];
__device__ __half g_qkvh[BSv * QS];       // packed q|k|v, row stride 1536
__device__ __half g_ctxh[BSv * Dv];
__device__ __half g_o1h[BSv * Dv];
__device__ __half g_ffnh[BSv * DFFv];
__device__ __half g_wqkvh[Dv * QS];       // packed weights [K=512][N=1536]
__device__ __half g_woh[Dv * Dv];
__device__ __half g_w1h[Dv * DFFv];
__device__ __half g_w2h[DFFv * Dv];
__device__ float g_bqkv[QS];              // packed bias
__device__ float g_res1[BSv * Dv];
__device__ float g_out1[BSv * Dv];
__device__ float g_res2[BSv * Dv];
__device__ float g_part1[512 * 2];
__device__ float g_part2[512 * 2];
__device__ float g_stats1[16 * 2];
__device__ float g_stats2[16 * 2];

// ---------------------------------------------------------------------------
// helpers
// ---------------------------------------------------------------------------
__device__ __forceinline__ void cp16(uint32_t dst, const void* src) {
    asm volatile("cp.async.cg.shared.global [%0], [%1], 16;"
                 :: "r"(dst), "l"(src));
}
__device__ __forceinline__ void cp_commit() {
    asm volatile("cp.async.commit_group;");
}
__device__ __forceinline__ void ldm_x4(uint32_t& r0, uint32_t& r1,
                                       uint32_t& r2, uint32_t& r3, uint32_t a) {
    asm volatile("ldmatrix.sync.aligned.m8n8.x4.shared.b16 {%0,%1,%2,%3}, [%4];"
                 : "=r"(r0), "=r"(r1), "=r"(r2), "=r"(r3) : "r"(a));
}
__device__ __forceinline__ void ldm_x4t(uint32_t& r0, uint32_t& r1,
                                        uint32_t& r2, uint32_t& r3, uint32_t a) {
    asm volatile("ldmatrix.sync.aligned.m8n8.x4.trans.shared.b16 {%0,%1,%2,%3}, [%4];"
                 : "=r"(r0), "=r"(r1), "=r"(r2), "=r"(r3) : "r"(a));
}
__device__ __forceinline__ void mma16(float* d, const uint32_t* a,
                                      uint32_t b0, uint32_t b1) {
    asm volatile(
        "mma.sync.aligned.m16n8k16.row.col.f32.f16.f16.f32 "
        "{%0,%1,%2,%3}, {%4,%5,%6,%7}, {%8,%9}, {%0,%1,%2,%3};"
        : "+f"(d[0]), "+f"(d[1]), "+f"(d[2]), "+f"(d[3])
        : "r"(a[0]), "r"(a[1]), "r"(a[2]), "r"(a[3]), "r"(b0), "r"(b1));
}
__device__ __forceinline__ uint32_t sptr(const void* p) {
    return (uint32_t)__cvta_generic_to_shared(p);
}

// ---------------------------------------------------------------------------
// fp16 tensor-core GEMM: CTA 128x128, BK=32, 256 threads, double-buffered.
// FUSE: epilogue adds residual Xres, writes fp32 res, emits per-CTA LN
// partials (sum, sumsq) -> part[blockIdx.y*gridDim.x + blockIdx.x].
// ---------------------------------------------------------------------------
template <int RELU, int HALF_OUT, int FUSE>
__global__ void __launch_bounds__(256) gemm_h(
    const __half* __restrict__ A, const __half* __restrict__ Bw,
    const float* __restrict__ bias, float* __restrict__ Cf,
    __half* __restrict__ Ch, const float* __restrict__ Xres,
    float* __restrict__ part, int N, int K)
{
    __shared__ __align__(16) __half As[2][128][40];
    __shared__ __align__(16) __half Bs[2][32][136];
    __shared__ float rsum[256], rsum2[256];

    const int tid = threadIdx.x;
    const int lane = tid & 31, wid = tid >> 5;
    const int qid = lane >> 2, tg = lane & 3;
    const int wm = (wid & 3) * 32, wn = (wid >> 2) * 64;
    const int m0 = blockIdx.y * 128, n0 = blockIdx.x * 128;

    float acc[2][8][4];
#pragma unroll
    for (int mt = 0; mt < 2; mt++)
#pragma unroll
        for (int nt = 0; nt < 8; nt++)
#pragma unroll
            for (int r = 0; r < 4; r++) acc[mt][nt][r] = 0.f;

    const int lr = lane & 7;
    const int lmh = (lane >> 3) & 1;
    const int lkh = lane >> 4;

#define LOAD_STAGE(st, k0)                                                     \
    {                                                                          \
        _Pragma("unroll")                                                      \
        for (int i = 0; i < 2; i++) {                                          \
            int c = tid + i * 256;                                             \
            int row = c >> 2, seg = c & 3;                                     \
            cp16(sptr(&As[st][row][seg * 8]),                                  \
                 A + (size_t)(m0 + row) * K + (k0) + seg * 8);                 \
            int rb = c >> 4, sb = c & 15;                                      \
            cp16(sptr(&Bs[st][rb][sb * 8]),                                    \
                 Bw + (size_t)((k0) + rb) * N + n0 + sb * 8);                  \
        }                                                                      \
    }

    const int nk = K >> 5;
    LOAD_STAGE(0, 0);
    cp_commit();

    for (int it = 0; it < nk; it++) {
        const int st = it & 1;
        if (it + 1 < nk) {
            LOAD_STAGE(st ^ 1, (it + 1) * 32);
            cp_commit();
            asm volatile("cp.async.wait_group 1;");
        } else {
            asm volatile("cp.async.wait_group 0;");
        }
        __syncthreads();

#pragma unroll
        for (int ko2 = 0; ko2 < 2; ko2++) {
            const int ko = ko2 * 16;
            uint32_t af[2][4];
#pragma unroll
            for (int mt = 0; mt < 2; mt++) {
                int mrow = wm + mt * 16 + lmh * 8 + lr;
                ldm_x4(af[mt][0], af[mt][1], af[mt][2], af[mt][3],
                       sptr(&As[st][mrow][ko + lkh * 8]));
            }
#pragma unroll
            for (int p = 0; p < 4; p++) {
                uint32_t b0, b1, b2, b3;
                int krow = ko + lmh * 8 + lr;
                int ncol = wn + p * 16 + lkh * 8;
                ldm_x4t(b0, b1, b2, b3, sptr(&Bs[st][krow][ncol]));
                mma16(acc[0][2 * p],     af[0], b0, b1);
                mma16(acc[1][2 * p],     af[1], b0, b1);
                mma16(acc[0][2 * p + 1], af[0], b2, b3);
                mma16(acc[1][2 * p + 1], af[1], b2, b3);
            }
        }
        __syncthreads();
    }
#undef LOAD_STAGE

    float s = 0.f, s2 = 0.f;
#pragma unroll
    for (int mt = 0; mt < 2; mt++) {
        int r_lo = m0 + wm + mt * 16 + qid;
        int r_hi = r_lo + 8;
#pragma unroll
        for (int nt = 0; nt < 8; nt++) {
            int col = n0 + wn + nt * 8 + 2 * tg;
            float bx = bias[col], by = bias[col + 1];
            float v0 = acc[mt][nt][0] + bx, v1 = acc[mt][nt][1] + by;
            float v2 = acc[mt][nt][2] + bx, v3 = acc[mt][nt][3] + by;
            if (RELU) {
                v0 = fmaxf(v0, 0.f); v1 = fmaxf(v1, 0.f);
                v2 = fmaxf(v2, 0.f); v3 = fmaxf(v3, 0.f);
            }
            if (FUSE) {
                float2 xa = *(const float2*)(Xres + (size_t)r_lo * N + col);
                float2 xb = *(const float2*)(Xres + (size_t)r_hi * N + col);
                v0 += xa.x; v1 += xa.y; v2 += xb.x; v3 += xb.y;
                s  += v0 + v1 + v2 + v3;
                s2 += v0 * v0 + v1 * v1 + v2 * v2 + v3 * v3;
            }
            if (HALF_OUT) {
                *(__half2*)(Ch + (size_t)r_lo * N + col) = __floats2half2_rn(v0, v1);
                *(__half2*)(Ch + (size_t)r_hi * N + col) = __floats2half2_rn(v2, v3);
            } else {
                *(float2*)(Cf + (size_t)r_lo * N + col) = make_float2(v0, v1);
                *(float2*)(Cf + (size_t)r_hi * N + col) = make_float2(v2, v3);
            }
        }
    }

    if (FUSE) {
        rsum[tid] = s; rsum2[tid] = s2;
        __syncthreads();
        for (int off = 128; off > 0; off >>= 1) {
            if (tid < off) { rsum[tid] += rsum[tid + off]; rsum2[tid] += rsum2[tid + off]; }
            __syncthreads();
        }
        if (tid == 0) {
            int pidx = blockIdx.y * gridDim.x + blockIdx.x;
            part[2 * pidx]     = rsum[0];
            part[2 * pidx + 1] = rsum2[0];
        }
    }
}

// float -> half conversion (n multiple of 1024)
__global__ void __launch_bounds__(256) f2h(const float* __restrict__ src,
                                           __half* __restrict__ dst)
{
    size_t i = ((size_t)blockIdx.x * 256 + threadIdx.x) * 4;
    float4 v = *(const float4*)(src + i);
    *(__half2*)(dst + i)     = __floats2half2_rn(v.x, v.y);
    *(__half2*)(dst + i + 2) = __floats2half2_rn(v.z, v.w);
}

// pack [512,512] fp32 weight into half at column offset `off`, row stride 1536
__global__ void __launch_bounds__(256) pack_w(const float* __restrict__ src,
                                              __half* __restrict__ dst, int off)
{
    size_t i = ((size_t)blockIdx.x * 256 + threadIdx.x) * 4;
    int row = (int)(i >> 9), col = (int)(i & 511);
    float4 v = *(const float4*)(src + i);
    __half* d = dst + (size_t)row * QS + off + col;
    *(__half2*)(d)     = __floats2half2_rn(v.x, v.y);
    *(__half2*)(d + 2) = __floats2half2_rn(v.z, v.w);
}

__global__ void pack_bias(const float* __restrict__ bq, const float* __restrict__ bk,
                          const float* __restrict__ bv, float* __restrict__ dst)
{
    int t = threadIdx.x;   // 512
    dst[t]        = bq[t];
    dst[512 + t]  = bk[t];
    dst[1024 + t] = bv[t];
}

// ---------------------------------------------------------------------------
// Flash attention, fp16 MMAs. grid = (S/128, B*H), block = 256 (8 warps).
// 128 query rows per CTA; 64-key K/V tiles double-buffered via cp.async.
// Q/K/V packed in qkv buffer, row stride QS=1536, offsets 0/512/1024.
// smem: K[2]:0..18432, V[2]:18432..36864, P/Q:36864..55296, mask:55296..59392
// ---------------------------------------------------------------------------
#define ATT_SMEM 59392

__global__ void __launch_bounds__(256) attn_h(
    const __half* __restrict__ QKV, const float* __restrict__ mask,
    __half* __restrict__ O)
{
    extern __shared__ __align__(16) char smraw[];
    __half* KsB = (__half*)smraw;                  // [2][64][72]
    __half* VsB = (__half*)(smraw + 18432);        // [2][64][72]
    __half* Psb = (__half*)(smraw + 36864);        // [128][72]
    float*  Msk = (float*)(smraw + 55296);         // [1024]

    const int tid = threadIdx.x;
    const int lane = tid & 31, wid = tid >> 5;
    const int qid = lane >> 2, tg = lane & 3;
    const int lr = lane & 7, lmh = (lane >> 3) & 1, lkh = lane >> 4;
    const int qt = blockIdx.x;
    const int b  = blockIdx.y >> 3;
    const int h  = blockIdx.y & 7;
    const size_t hcol = (size_t)h * 64;
    const size_t brow = (size_t)b * Sv;

#define LOAD_KV(st, kt)                                                        \
    {                                                                          \
        _Pragma("unroll")                                                      \
        for (int i = 0; i < 2; i++) {                                          \
            int c = tid + i * 256;                                             \
            int row = c >> 3, seg = c & 7;                                     \
            size_t g = (brow + (kt) * 64 + row) * QS + hcol + seg * 8;         \
            cp16(sptr(KsB + (st) * 4608 + row * 72 + seg * 8), QKV + g + 512); \
            cp16(sptr(VsB + (st) * 4608 + row * 72 + seg * 8), QKV + g + 1024);\
        }                                                                      \
    }

    LOAD_KV(0, 0);
    cp_commit();

    // mask row (pre-scaled by -1e9)
#pragma unroll
    for (int i = 0; i < 4; i++)
        Msk[tid + i * 256] = mask[b * Sv + tid + i * 256] * -1e9f;

    // stage Q tile (128 x 64) into P region
#pragma unroll
    for (int i = 0; i < 4; i++) {
        int c = tid + i * 256;
        int row = c >> 3, seg = c & 7;
        *(uint4*)(Psb + row * 72 + seg * 8) =
            *(const uint4*)(QKV + (brow + qt * 128 + row) * QS + hcol + seg * 8);
    }
    __syncthreads();

    // Q fragments: 4 k16-steps x 4 regs (warp's 16 rows)
    const int rm = wid * 16 + qid;
    uint32_t qf[4][4];
#pragma unroll
    for (int kk = 0; kk < 4; kk++) {
        qf[kk][0] = *(const uint32_t*)(Psb + rm * 72 + kk * 16 + 2 * tg);
        qf[kk][1] = *(const uint32_t*)(Psb + (rm + 8) * 72 + kk * 16 + 2 * tg);
        qf[kk][2] = *(const uint32_t*)(Psb + rm * 72 + kk * 16 + 2 * tg + 8);
        qf[kk][3] = *(const uint32_t*)(Psb + (rm + 8) * 72 + kk * 16 + 2 * tg + 8);
    }

    float m_lo = -1e30f, m_hi = -1e30f, l_lo = 0.f, l_hi = 0.f;
    float of[8][4];
#pragma unroll
    for (int nt = 0; nt < 8; nt++)
#pragma unroll
        for (int r = 0; r < 4; r++) of[nt][r] = 0.f;

    for (int kt = 0; kt < 16; kt++) {
        const int st = kt & 1;
        if (kt + 1 < 16) {
            LOAD_KV(st ^ 1, kt + 1);
            cp_commit();
            asm volatile("cp.async.wait_group 1;");
        } else {
            asm volatile("cp.async.wait_group 0;");
        }
        __syncthreads();

        // S = Q @ K^T
        float sc[8][4];
#pragma unroll
        for (int nt = 0; nt < 8; nt++) {
#pragma unroll
            for (int r = 0; r < 4; r++) sc[nt][r] = 0.f;
            const __half* kr = KsB + st * 4608 + (nt * 8 + qid) * 72;
#pragma unroll
            for (int kk = 0; kk < 4; kk++) {
                uint32_t b0 = *(const uint32_t*)(kr + kk * 16 + 2 * tg);
                uint32_t b1 = *(const uint32_t*)(kr + kk * 16 + 2 * tg + 8);
                mma16(sc[nt], qf[kk], b0, b1);
            }
        }

        // scale + mask, online softmax
        float tmax_lo = -1e30f, tmax_hi = -1e30f;
#pragma unroll
        for (int nt = 0; nt < 8; nt++) {
            int col = kt * 64 + nt * 8 + 2 * tg;
            float mk0 = Msk[col], mk1 = Msk[col + 1];
            sc[nt][0] = sc[nt][0] * 0.125f + mk0;
            sc[nt][1] = sc[nt][1] * 0.125f + mk1;
            sc[nt][2] = sc[nt][2] * 0.125f + mk0;
            sc[nt][3] = sc[nt][3] * 0.125f + mk1;
            tmax_lo = fmaxf(tmax_lo, fmaxf(sc[nt][0], sc[nt][1]));
            tmax_hi = fmaxf(tmax_hi, fmaxf(sc[nt][2], sc[nt][3]));
        }
        tmax_lo = fmaxf(tmax_lo, __shfl_xor_sync(0xffffffffu, tmax_lo, 1));
        tmax_lo = fmaxf(tmax_lo, __shfl_xor_sync(0xffffffffu, tmax_lo, 2));
        tmax_hi = fmaxf(tmax_hi, __shfl_xor_sync(0xffffffffu, tmax_hi, 1));
        tmax_hi = fmaxf(tmax_hi, __shfl_xor_sync(0xffffffffu, tmax_hi, 2));

        float mn_lo = fmaxf(m_lo, tmax_lo);
        float mn_hi = fmaxf(m_hi, tmax_hi);
        float al_lo = __expf(m_lo - mn_lo);
        float al_hi = __expf(m_hi - mn_hi);
        m_lo = mn_lo; m_hi = mn_hi;

        float ps_lo = 0.f, ps_hi = 0.f;
#pragma unroll
        for (int nt = 0; nt < 8; nt++) {
            sc[nt][0] = __expf(sc[nt][0] - mn_lo);
            sc[nt][1] = __expf(sc[nt][1] - mn_lo);
            sc[nt][2] = __expf(sc[nt][2] - mn_hi);
            sc[nt][3] = __expf(sc[nt][3] - mn_hi);
            ps_lo += sc[nt][0] + sc[nt][1];
            ps_hi += sc[nt][2] + sc[nt][3];
        }
        ps_lo += __shfl_xor_sync(0xffffffffu, ps_lo, 1);
        ps_lo += __shfl_xor_sync(0xffffffffu, ps_lo, 2);
        ps_hi += __shfl_xor_sync(0xffffffffu, ps_hi, 1);
        ps_hi += __shfl_xor_sync(0xffffffffu, ps_hi, 2);
        l_lo = l_lo * al_lo + ps_lo;
        l_hi = l_hi * al_hi + ps_hi;

        // rescale O, stage P as half (warp-private rows)
#pragma unroll
        for (int nt = 0; nt < 8; nt++) {
            of[nt][0] *= al_lo; of[nt][1] *= al_lo;
            of[nt][2] *= al_hi; of[nt][3] *= al_hi;
            *(__half2*)(Psb + rm * 72 + nt * 8 + 2 * tg) =
                __floats2half2_rn(sc[nt][0], sc[nt][1]);
            *(__half2*)(Psb + (rm + 8) * 72 + nt * 8 + 2 * tg) =
                __floats2half2_rn(sc[nt][2], sc[nt][3]);
        }
        __syncwarp();

        // O += P @ V
#pragma unroll
        for (int kk = 0; kk < 4; kk++) {
            uint32_t pa[4];
            pa[0] = *(const uint32_t*)(Psb + rm * 72 + kk * 16 + 2 * tg);
            pa[1] = *(const uint32_t*)(Psb + (rm + 8) * 72 + kk * 16 + 2 * tg);
            pa[2] = *(const uint32_t*)(Psb + rm * 72 + kk * 16 + 2 * tg + 8);
            pa[3] = *(const uint32_t*)(Psb + (rm + 8) * 72 + kk * 16 + 2 * tg + 8);
#pragma unroll
            for (int p = 0; p < 4; p++) {
                uint32_t b0, b1, b2, b3;
                int krow = kk * 16 + lmh * 8 + lr;
                int ncol = p * 16 + lkh * 8;
                ldm_x4t(b0, b1, b2, b3,
                        sptr(VsB + st * 4608 + krow * 72 + ncol));
                mma16(of[2 * p],     pa, b0, b1);
                mma16(of[2 * p + 1], pa, b2, b3);
            }
        }
        __syncthreads();
    }
#undef LOAD_KV

    // write normalized output as half (feeds O-projection, row stride Dv)
    float inv_lo = 1.f / l_lo, inv_hi = 1.f / l_hi;
    size_t r_lo = brow + qt * 128 + rm;
    size_t r_hi = r_lo + 8;
#pragma unroll
    for (int nt = 0; nt < 8; nt++) {
        size_t col = hcol + nt * 8 + 2 * tg;
        *(__half2*)(O + r_lo * Dv + col) =
            __floats2half2_rn(of[nt][0] * inv_lo, of[nt][1] * inv_lo);
        *(__half2*)(O + r_hi * Dv + col) =
            __floats2half2_rn(of[nt][2] * inv_hi, of[nt][3] * inv_hi);
    }
}

// ---------------------------------------------------------------------------
// LayerNorm finalize (32 partials per batch) + apply
// ---------------------------------------------------------------------------
__global__ void ln_finalize32(const float* __restrict__ part,
                              float* __restrict__ stats)
{
    const int b = blockIdx.x;
    const int t = threadIdx.x;    // 32
    float s  = part[(b * 32 + t) * 2 + 0];
    float s2 = part[(b * 32 + t) * 2 + 1];
#pragma unroll
    for (int m = 16; m; m >>= 1) {
        s  += __shfl_xor_sync(0xffffffffu, s, m);
        s2 += __shfl_xor_sync(0xffffffffu, s2, m);
    }
    if (t == 0) {
        float n = (float)SDv;
        float mean = s / n;
        float var  = s2 / n - mean * mean;
        stats[b * 2 + 0] = mean;
        stats[b * 2 + 1] = rsqrtf(var + 1e-5f);
    }
}

template <int HALF_COPY>
__global__ void __launch_bounds__(256) ln_apply(
    const float* __restrict__ R, const float* __restrict__ stats,
    const float* __restrict__ W, const float* __restrict__ Bb,
    float* __restrict__ out, __half* __restrict__ outh)
{
    size_t i4 = (size_t)blockIdx.x * 256 + threadIdx.x;
    size_t e  = i4 * 4;
    int b  = (int)(e >> 19);
    int sd = (int)(e & (SDv - 1));
    float mean = stats[b * 2 + 0];
    float rstd = stats[b * 2 + 1];
    float4 r  = *(const float4*)(R + e);
    float4 w4 = *(const float4*)(W + sd);
    float4 b4 = *(const float4*)(Bb + sd);
    float4 y;
    y.x = (r.x - mean) * rstd * w4.x + b4.x;
    y.y = (r.y - mean) * rstd * w4.y + b4.y;
    y.z = (r.z - mean) * rstd * w4.z + b4.z;
    y.w = (r.w - mean) * rstd * w4.w + b4.w;
    *(float4*)(out + e) = y;
    if (HALF_COPY) {
        *(__half2*)(outh + e)     = __floats2half2_rn(y.x, y.y);
        *(__half2*)(outh + e + 2) = __floats2half2_rn(y.z, y.w);
    }
}

// ---------------------------------------------------------------------------
extern "C" void kernel_launch(void* const* d_in, const int* in_sizes, int n_in,
                              void* d_out, int out_size)
{
    const float* x    = (const float*)d_in[0];
    const float* mask = (const float*)d_in[1];
    const float* wq   = (const float*)d_in[2];
    const float* bq   = (const float*)d_in[3];
    const float* wk   = (const float*)d_in[4];
    const float* bk   = (const float*)d_in[5];
    const float* wv   = (const float*)d_in[6];
    const float* bv   = (const float*)d_in[7];
    const float* wo   = (const float*)d_in[8];
    const float* bo   = (const float*)d_in[9];
    const float* w1   = (const float*)d_in[10];
    const float* b1   = (const float*)d_in[11];
    const float* w2   = (const float*)d_in[12];
    const float* b2   = (const float*)d_in[13];
    const float* ln1w = (const float*)d_in[14];
    const float* ln1b = (const float*)d_in[15];
    const float* ln2w = (const float*)d_in[16];
    const float* ln2b = (const float*)d_in[17];
    float* out = (float*)d_out;

    void* p;
    cudaGetSymbolAddress(&p, g_xh);      __half* xh    = (__half*)p;
    cudaGetSymbolAddress(&p, g_qkvh);    __half* qkvh  = (__half*)p;
    cudaGetSymbolAddress(&p, g_ctxh);    __half* ctxh  = (__half*)p;
    cudaGetSymbolAddress(&p, g_o1h);     __half* o1h   = (__half*)p;
    cudaGetSymbolAddress(&p, g_ffnh);    __half* ffnh  = (__half*)p;
    cudaGetSymbolAddress(&p, g_wqkvh);   __half* wqkvh = (__half*)p;
    cudaGetSymbolAddress(&p, g_woh);     __half* woh   = (__half*)p;
    cudaGetSymbolAddress(&p, g_w1h);     __half* w1h   = (__half*)p;
    cudaGetSymbolAddress(&p, g_w2h);     __half* w2h   = (__half*)p;
    cudaGetSymbolAddress(&p, g_bqkv);    float* bqkv   = (float*)p;
    cudaGetSymbolAddress(&p, g_res1);    float* res1   = (float*)p;
    cudaGetSymbolAddress(&p, g_out1);    float* out1   = (float*)p;
    cudaGetSymbolAddress(&p, g_res2);    float* res2   = (float*)p;
    cudaGetSymbolAddress(&p, g_part1);   float* part1  = (float*)p;
    cudaGetSymbolAddress(&p, g_part2);   float* part2  = (float*)p;
    cudaGetSymbolAddress(&p, g_stats1);  float* stats1 = (float*)p;
    cudaGetSymbolAddress(&p, g_stats2);  float* stats2 = (float*)p;

    cudaFuncSetAttribute(attn_h,
                         cudaFuncAttributeMaxDynamicSharedMemorySize, ATT_SMEM);

    dim3 blk(256);
    dim3 gQKV(QS / 128, BSv / 128);    // (12, 128)
    dim3 gD(Dv / 128, BSv / 128);      // (4, 128)
    dim3 gF(DFFv / 128, BSv / 128);    // (16, 128)
    dim3 gAttn(Sv / 128, Bv * 8);      // (8, 128)
    int  gApply = (BSv * Dv / 4) / 256;

    // conversions / packing
    f2h<<<(BSv * Dv) / 1024, 256>>>(x, xh);
    pack_w<<<(Dv * Dv) / 1024, 256>>>(wq, wqkvh, 0);
    pack_w<<<(Dv * Dv) / 1024, 256>>>(wk, wqkvh, 512);
    pack_w<<<(Dv * Dv) / 1024, 256>>>(wv, wqkvh, 1024);
    pack_bias<<<1, 512>>>(bq, bk, bv, bqkv);
    f2h<<<(Dv * Dv) / 1024, 256>>>(wo, woh);
    f2h<<<(Dv * DFFv) / 1024, 256>>>(w1, w1h);
    f2h<<<(Dv * DFFv) / 1024, 256>>>(w2, w2h);

    // fused QKV projection (half out, packed)
    gemm_h<0, 1, 0><<<gQKV, blk>>>(xh, wqkvh, bqkv, nullptr, qkvh,
                                   nullptr, nullptr, QS, Dv);

    // attention
    attn_h<<<gAttn, blk, ATT_SMEM>>>(qkvh, mask, ctxh);

    // O-projection fused with residual + LN1 partials
    gemm_h<0, 0, 1><<<gD, blk>>>(ctxh, woh, bo, res1, nullptr,
                                 x, part1, Dv, Dv);
    ln_finalize32<<<Bv, 32>>>(part1, stats1);
    ln_apply<1><<<gApply, blk>>>(res1, stats1, ln1w, ln1b, out1, o1h);

    // FFN1 (half out)
    gemm_h<1, 1, 0><<<gF, blk>>>(o1h, w1h, b1, nullptr, ffnh,
                                 nullptr, nullptr, DFFv, Dv);
    // FFN2 fused with residual + LN2 partials
    gemm_h<0, 0, 1><<<gD, blk>>>(ffnh, w2h, b2, res2, nullptr,
                                 out1, part2, Dv, DFFv);
    ln_finalize32<<<Bv, 32>>>(part2, stats2);
    ln_apply<0><<<gApply, blk>>>(res2, stats2, ln2w, ln2b, out, nullptr);
}

// round 6
// speedup vs baseline: 6.3575x; 1.0126x over previous
#include <cuda_runtime.h>
#include <cuda_fp16.h>
#include <cstdint>
#include <math.h>

// Problem constants
static const int Bv   = 16;
static const int Sv   = 1024;
static const int Dv   = 512;
static const int DFFv = 2048;
static const int BSv  = Bv * Sv;        // 16384
static const int SDv  = Sv * Dv;        // 524288 = 2^19
static const int QS   = 1536;           // packed QKV row stride

// ---------------- scratch (device globals; no allocation allowed) ----------
__device__ __half g_xh[BSv * Dv];
__device__ __half g_qkvh[BSv * QS];       // packed q|k|v, row stride 1536
__device__ __half g_ctxh[BSv * Dv];
__device__ __half g_o1h[BSv * Dv];
__device__ __half g_ffnh[BSv * DFFv];
__device__ __half g_wqkvh[Dv * QS];       // packed weights [K=512][N=1536]
__device__ __half g_woh[Dv * Dv];
__device__ __half g_w1h[Dv * DFFv];
__device__ __half g_w2h[DFFv * Dv];
__device__ float g_bqkv[QS];              // packed bias
__device__ float g_res1[BSv * Dv];
__device__ float g_out1[BSv * Dv];
__device__ float g_res2[BSv * Dv];
__device__ float g_part1[512 * 2];
__device__ float g_part2[512 * 2];
__device__ float g_stats1[16 * 2];
__device__ float g_stats2[16 * 2];

// ---------------------------------------------------------------------------
// helpers
// ---------------------------------------------------------------------------
__device__ __forceinline__ void cp16(uint32_t dst, const void* src) {
    asm volatile("cp.async.cg.shared.global [%0], [%1], 16;"
                 :: "r"(dst), "l"(src));
}
__device__ __forceinline__ void cp_commit() {
    asm volatile("cp.async.commit_group;");
}
__device__ __forceinline__ void ldm_x4(uint32_t& r0, uint32_t& r1,
                                       uint32_t& r2, uint32_t& r3, uint32_t a) {
    asm volatile("ldmatrix.sync.aligned.m8n8.x4.shared.b16 {%0,%1,%2,%3}, [%4];"
                 : "=r"(r0), "=r"(r1), "=r"(r2), "=r"(r3) : "r"(a));
}
__device__ __forceinline__ void ldm_x4t(uint32_t& r0, uint32_t& r1,
                                        uint32_t& r2, uint32_t& r3, uint32_t a) {
    asm volatile("ldmatrix.sync.aligned.m8n8.x4.trans.shared.b16 {%0,%1,%2,%3}, [%4];"
                 : "=r"(r0), "=r"(r1), "=r"(r2), "=r"(r3) : "r"(a));
}
__device__ __forceinline__ void mma16(float* d, const uint32_t* a,
                                      uint32_t b0, uint32_t b1) {
    asm volatile(
        "mma.sync.aligned.m16n8k16.row.col.f32.f16.f16.f32 "
        "{%0,%1,%2,%3}, {%4,%5,%6,%7}, {%8,%9}, {%0,%1,%2,%3};"
        : "+f"(d[0]), "+f"(d[1]), "+f"(d[2]), "+f"(d[3])
        : "r"(a[0]), "r"(a[1]), "r"(a[2]), "r"(a[3]), "r"(b0), "r"(b1));
}
__device__ __forceinline__ uint32_t sptr(const void* p) {
    return (uint32_t)__cvta_generic_to_shared(p);
}

// ---------------------------------------------------------------------------
// fp16 tensor-core GEMM: CTA 128x128, BK=32, 256 threads, 3-stage cp.async
// pipeline, ONE __syncthreads per mainloop iteration.
// Dynamic smem: 3 stages of (A[128][40] + B[32][136]) halfs = 56832 bytes.
// FUSE: epilogue adds residual Xres, writes fp32, per-CTA LN partials.
// ---------------------------------------------------------------------------
#define ASTG (128 * 40)            // halfs per A stage
#define BSTG (32 * 136)            // halfs per B stage
#define STG  (ASTG + BSTG)         // 9472 halfs = 18944 B
#define GEMM_SMEM (3 * STG * 2)    // 56832 B

template <int RELU, int HALF_OUT, int FUSE>
__global__ void __launch_bounds__(256) gemm_h(
    const __half* __restrict__ A, const __half* __restrict__ Bw,
    const float* __restrict__ bias, float* __restrict__ Cf,
    __half* __restrict__ Ch, const float* __restrict__ Xres,
    float* __restrict__ part, int N, int K)
{
    extern __shared__ __align__(16) __half smh[];

    const int tid = threadIdx.x;
    const int lane = tid & 31, wid = tid >> 5;
    const int qid = lane >> 2, tg = lane & 3;
    const int wm = (wid & 3) * 32, wn = (wid >> 2) * 64;
    const int m0 = blockIdx.y * 128, n0 = blockIdx.x * 128;

    float acc[2][8][4];
#pragma unroll
    for (int mt = 0; mt < 2; mt++)
#pragma unroll
        for (int nt = 0; nt < 8; nt++)
#pragma unroll
            for (int r = 0; r < 4; r++) acc[mt][nt][r] = 0.f;

    const int lr = lane & 7;
    const int lmh = (lane >> 3) & 1;
    const int lkh = lane >> 4;

    // per-thread load coordinates (computed once)
    const int a_row0 = tid >> 2,  a_seg = (tid & 3) * 8;
    const int b_row0 = tid >> 4,  b_seg = (tid & 15) * 8;

#define LOAD_STAGE(st, k0)                                                     \
    {                                                                          \
        __half* As_ = smh + (st) * STG;                                        \
        __half* Bs_ = smh + (st) * STG + ASTG;                                 \
        cp16(sptr(As_ + a_row0 * 40 + a_seg),                                  \
             A + (size_t)(m0 + a_row0) * K + (k0) + a_seg);                    \
        cp16(sptr(As_ + (a_row0 + 64) * 40 + a_seg),                           \
             A + (size_t)(m0 + a_row0 + 64) * K + (k0) + a_seg);               \
        cp16(sptr(Bs_ + b_row0 * 136 + b_seg),                                 \
             Bw + (size_t)((k0) + b_row0) * N + n0 + b_seg);                   \
        cp16(sptr(Bs_ + (b_row0 + 16) * 136 + b_seg),                          \
             Bw + (size_t)((k0) + b_row0 + 16) * N + n0 + b_seg);              \
    }

    const int nk = K >> 5;
    LOAD_STAGE(0, 0); cp_commit();
    LOAD_STAGE(1, 32); cp_commit();

    for (int it = 0; it < nk; it++) {
        const int st = it % 3;
        asm volatile("cp.async.wait_group 1;");
        __syncthreads();

        const __half* As_ = smh + st * STG;
        const __half* Bs_ = smh + st * STG + ASTG;

#pragma unroll
        for (int ko2 = 0; ko2 < 2; ko2++) {
            const int ko = ko2 * 16;
            uint32_t af[2][4];
#pragma unroll
            for (int mt = 0; mt < 2; mt++) {
                int mrow = wm + mt * 16 + lmh * 8 + lr;
                ldm_x4(af[mt][0], af[mt][1], af[mt][2], af[mt][3],
                       sptr(As_ + mrow * 40 + ko + lkh * 8));
            }
#pragma unroll
            for (int p = 0; p < 4; p++) {
                uint32_t b0, b1, b2, b3;
                int krow = ko + lmh * 8 + lr;
                int ncol = wn + p * 16 + lkh * 8;
                ldm_x4t(b0, b1, b2, b3, sptr(Bs_ + krow * 136 + ncol));
                mma16(acc[0][2 * p],     af[0], b0, b1);
                mma16(acc[1][2 * p],     af[1], b0, b1);
                mma16(acc[0][2 * p + 1], af[0], b2, b3);
                mma16(acc[1][2 * p + 1], af[1], b2, b3);
            }
        }

        if (it + 2 < nk) {
            LOAD_STAGE((it + 2) % 3, (it + 2) * 32);
            cp_commit();
        } else {
            cp_commit();   // keep group count in step for wait_group 1
        }
    }
#undef LOAD_STAGE

    float s = 0.f, s2 = 0.f;
#pragma unroll
    for (int mt = 0; mt < 2; mt++) {
        int r_lo = m0 + wm + mt * 16 + qid;
        int r_hi = r_lo + 8;
#pragma unroll
        for (int nt = 0; nt < 8; nt++) {
            int col = n0 + wn + nt * 8 + 2 * tg;
            float bx = bias[col], by = bias[col + 1];
            float v0 = acc[mt][nt][0] + bx, v1 = acc[mt][nt][1] + by;
            float v2 = acc[mt][nt][2] + bx, v3 = acc[mt][nt][3] + by;
            if (RELU) {
                v0 = fmaxf(v0, 0.f); v1 = fmaxf(v1, 0.f);
                v2 = fmaxf(v2, 0.f); v3 = fmaxf(v3, 0.f);
            }
            if (FUSE) {
                float2 xa = *(const float2*)(Xres + (size_t)r_lo * N + col);
                float2 xb = *(const float2*)(Xres + (size_t)r_hi * N + col);
                v0 += xa.x; v1 += xa.y; v2 += xb.x; v3 += xb.y;
                s  += v0 + v1 + v2 + v3;
                s2 += v0 * v0 + v1 * v1 + v2 * v2 + v3 * v3;
            }
            if (HALF_OUT) {
                *(__half2*)(Ch + (size_t)r_lo * N + col) = __floats2half2_rn(v0, v1);
                *(__half2*)(Ch + (size_t)r_hi * N + col) = __floats2half2_rn(v2, v3);
            } else {
                *(float2*)(Cf + (size_t)r_lo * N + col) = make_float2(v0, v1);
                *(float2*)(Cf + (size_t)r_hi * N + col) = make_float2(v2, v3);
            }
        }
    }

    if (FUSE) {
        float* rsum  = (float*)smh;          // reuse stage smem
        float* rsum2 = rsum + 256;
        __syncthreads();                     // all warps done with stages
        rsum[tid] = s; rsum2[tid] = s2;
        __syncthreads();
        for (int off = 128; off > 0; off >>= 1) {
            if (tid < off) { rsum[tid] += rsum[tid + off]; rsum2[tid] += rsum2[tid + off]; }
            __syncthreads();
        }
        if (tid == 0) {
            int pidx = blockIdx.y * gridDim.x + blockIdx.x;
            part[2 * pidx]     = rsum[0];
            part[2 * pidx + 1] = rsum2[0];
        }
    }
}

// ---------------------------------------------------------------------------
// Single prep kernel: f2h(x), f2h(wo,w1,w2), pack(wq,wk,wv), pack bias.
// 256 threads, 1024 elements per block. Segment dispatch on blockIdx.x.
// ---------------------------------------------------------------------------
__global__ void __launch_bounds__(256) prep(
    const float* __restrict__ x,
    const float* __restrict__ wq, const float* __restrict__ wk,
    const float* __restrict__ wv, const float* __restrict__ wo,
    const float* __restrict__ w1, const float* __restrict__ w2,
    const float* __restrict__ bq, const float* __restrict__ bk,
    const float* __restrict__ bv,
    __half* __restrict__ xh, __half* __restrict__ wqkvh,
    __half* __restrict__ woh, __half* __restrict__ w1h,
    __half* __restrict__ w2h, float* __restrict__ bqkv)
{
    const int blk = blockIdx.x;
    const int tid = threadIdx.x;

    if (blk < 10496) {
        // plain f2h segments
        const float* src; __half* dst; size_t base;
        if (blk < 8192)       { src = x;  dst = xh;  base = (size_t)blk * 1024; }
        else if (blk < 8448)  { src = wo; dst = woh; base = (size_t)(blk - 8192) * 1024; }
        else if (blk < 9472)  { src = w1; dst = w1h; base = (size_t)(blk - 8448) * 1024; }
        else                  { src = w2; dst = w2h; base = (size_t)(blk - 9472) * 1024; }
        size_t i = base + (size_t)tid * 4;
        float4 v = *(const float4*)(src + i);
        *(__half2*)(dst + i)     = __floats2half2_rn(v.x, v.y);
        *(__half2*)(dst + i + 2) = __floats2half2_rn(v.z, v.w);
    } else if (blk < 11264) {
        // pack wq/wk/wv into wqkvh ([512][1536], col offsets 0/512/1024)
        const float* src; int off; int sb;
        if (blk < 10752)      { src = wq; off = 0;    sb = blk - 10496; }
        else if (blk < 11008) { src = wk; off = 512;  sb = blk - 10752; }
        else                  { src = wv; off = 1024; sb = blk - 11008; }
        size_t i = (size_t)sb * 1024 + (size_t)tid * 4;
        int row = (int)(i >> 9), col = (int)(i & 511);
        float4 v = *(const float4*)(src + i);
        __half* d = wqkvh + (size_t)row * QS + off + col;
        *(__half2*)(d)     = __floats2half2_rn(v.x, v.y);
        *(__half2*)(d + 2) = __floats2half2_rn(v.z, v.w);
    } else {
        // bias pack
        for (int i = tid; i < 1536; i += 256)
            bqkv[i] = (i < 512) ? bq[i] : (i < 1024) ? bk[i - 512] : bv[i - 1024];
    }
}

// ---------------------------------------------------------------------------
// Flash attention, fp16 MMAs. grid = (S/128, B*H), block = 256 (8 warps).
// ---------------------------------------------------------------------------
#define ATT_SMEM 59392

__global__ void __launch_bounds__(256) attn_h(
    const __half* __restrict__ QKV, const float* __restrict__ mask,
    __half* __restrict__ O)
{
    extern __shared__ __align__(16) char smraw[];
    __half* KsB = (__half*)smraw;                  // [2][64][72]
    __half* VsB = (__half*)(smraw + 18432);        // [2][64][72]
    __half* Psb = (__half*)(smraw + 36864);        // [128][72]
    float*  Msk = (float*)(smraw + 55296);         // [1024]

    const int tid = threadIdx.x;
    const int lane = tid & 31, wid = tid >> 5;
    const int qid = lane >> 2, tg = lane & 3;
    const int lr = lane & 7, lmh = (lane >> 3) & 1, lkh = lane >> 4;
    const int qt = blockIdx.x;
    const int b  = blockIdx.y >> 3;
    const int h  = blockIdx.y & 7;
    const size_t hcol = (size_t)h * 64;
    const size_t brow = (size_t)b * Sv;

#define LOAD_KV(st, kt)                                                        \
    {                                                                          \
        _Pragma("unroll")                                                      \
        for (int i = 0; i < 2; i++) {                                          \
            int c = tid + i * 256;                                             \
            int row = c >> 3, seg = c & 7;                                     \
            size_t g = (brow + (kt) * 64 + row) * QS + hcol + seg * 8;         \
            cp16(sptr(KsB + (st) * 4608 + row * 72 + seg * 8), QKV + g + 512); \
            cp16(sptr(VsB + (st) * 4608 + row * 72 + seg * 8), QKV + g + 1024);\
        }                                                                      \
    }

    LOAD_KV(0, 0);
    cp_commit();

#pragma unroll
    for (int i = 0; i < 4; i++)
        Msk[tid + i * 256] = mask[b * Sv + tid + i * 256] * -1e9f;

#pragma unroll
    for (int i = 0; i < 4; i++) {
        int c = tid + i * 256;
        int row = c >> 3, seg = c & 7;
        *(uint4*)(Psb + row * 72 + seg * 8) =
            *(const uint4*)(QKV + (brow + qt * 128 + row) * QS + hcol + seg * 8);
    }
    __syncthreads();

    const int rm = wid * 16 + qid;
    uint32_t qf[4][4];
#pragma unroll
    for (int kk = 0; kk < 4; kk++) {
        qf[kk][0] = *(const uint32_t*)(Psb + rm * 72 + kk * 16 + 2 * tg);
        qf[kk][1] = *(const uint32_t*)(Psb + (rm + 8) * 72 + kk * 16 + 2 * tg);
        qf[kk][2] = *(const uint32_t*)(Psb + rm * 72 + kk * 16 + 2 * tg + 8);
        qf[kk][3] = *(const uint32_t*)(Psb + (rm + 8) * 72 + kk * 16 + 2 * tg + 8);
    }

    float m_lo = -1e30f, m_hi = -1e30f, l_lo = 0.f, l_hi = 0.f;
    float of[8][4];
#pragma unroll
    for (int nt = 0; nt < 8; nt++)
#pragma unroll
        for (int r = 0; r < 4; r++) of[nt][r] = 0.f;

    for (int kt = 0; kt < 16; kt++) {
        const int st = kt & 1;
        if (kt + 1 < 16) {
            LOAD_KV(st ^ 1, kt + 1);
            cp_commit();
            asm volatile("cp.async.wait_group 1;");
        } else {
            asm volatile("cp.async.wait_group 0;");
        }
        __syncthreads();

        float sc[8][4];
#pragma unroll
        for (int nt = 0; nt < 8; nt++) {
#pragma unroll
            for (int r = 0; r < 4; r++) sc[nt][r] = 0.f;
            const __half* kr = KsB + st * 4608 + (nt * 8 + qid) * 72;
#pragma unroll
            for (int kk = 0; kk < 4; kk++) {
                uint32_t b0 = *(const uint32_t*)(kr + kk * 16 + 2 * tg);
                uint32_t b1 = *(const uint32_t*)(kr + kk * 16 + 2 * tg + 8);
                mma16(sc[nt], qf[kk], b0, b1);
            }
        }

        float tmax_lo = -1e30f, tmax_hi = -1e30f;
#pragma unroll
        for (int nt = 0; nt < 8; nt++) {
            int col = kt * 64 + nt * 8 + 2 * tg;
            float mk0 = Msk[col], mk1 = Msk[col + 1];
            sc[nt][0] = sc[nt][0] * 0.125f + mk0;
            sc[nt][1] = sc[nt][1] * 0.125f + mk1;
            sc[nt][2] = sc[nt][2] * 0.125f + mk0;
            sc[nt][3] = sc[nt][3] * 0.125f + mk1;
            tmax_lo = fmaxf(tmax_lo, fmaxf(sc[nt][0], sc[nt][1]));
            tmax_hi = fmaxf(tmax_hi, fmaxf(sc[nt][2], sc[nt][3]));
        }
        tmax_lo = fmaxf(tmax_lo, __shfl_xor_sync(0xffffffffu, tmax_lo, 1));
        tmax_lo = fmaxf(tmax_lo, __shfl_xor_sync(0xffffffffu, tmax_lo, 2));
        tmax_hi = fmaxf(tmax_hi, __shfl_xor_sync(0xffffffffu, tmax_hi, 1));
        tmax_hi = fmaxf(tmax_hi, __shfl_xor_sync(0xffffffffu, tmax_hi, 2));

        float mn_lo = fmaxf(m_lo, tmax_lo);
        float mn_hi = fmaxf(m_hi, tmax_hi);
        float al_lo = __expf(m_lo - mn_lo);
        float al_hi = __expf(m_hi - mn_hi);
        m_lo = mn_lo; m_hi = mn_hi;

        float ps_lo = 0.f, ps_hi = 0.f;
#pragma unroll
        for (int nt = 0; nt < 8; nt++) {
            sc[nt][0] = __expf(sc[nt][0] - mn_lo);
            sc[nt][1] = __expf(sc[nt][1] - mn_lo);
            sc[nt][2] = __expf(sc[nt][2] - mn_hi);
            sc[nt][3] = __expf(sc[nt][3] - mn_hi);
            ps_lo += sc[nt][0] + sc[nt][1];
            ps_hi += sc[nt][2] + sc[nt][3];
        }
        ps_lo += __shfl_xor_sync(0xffffffffu, ps_lo, 1);
        ps_lo += __shfl_xor_sync(0xffffffffu, ps_lo, 2);
        ps_hi += __shfl_xor_sync(0xffffffffu, ps_hi, 1);
        ps_hi += __shfl_xor_sync(0xffffffffu, ps_hi, 2);
        l_lo = l_lo * al_lo + ps_lo;
        l_hi = l_hi * al_hi + ps_hi;

#pragma unroll
        for (int nt = 0; nt < 8; nt++) {
            of[nt][0] *= al_lo; of[nt][1] *= al_lo;
            of[nt][2] *= al_hi; of[nt][3] *= al_hi;
            *(__half2*)(Psb + rm * 72 + nt * 8 + 2 * tg) =
                __floats2half2_rn(sc[nt][0], sc[nt][1]);
            *(__half2*)(Psb + (rm + 8) * 72 + nt * 8 + 2 * tg) =
                __floats2half2_rn(sc[nt][2], sc[nt][3]);
        }
        __syncwarp();

#pragma unroll
        for (int kk = 0; kk < 4; kk++) {
            uint32_t pa[4];
            pa[0] = *(const uint32_t*)(Psb + rm * 72 + kk * 16 + 2 * tg);
            pa[1] = *(const uint32_t*)(Psb + (rm + 8) * 72 + kk * 16 + 2 * tg);
            pa[2] = *(const uint32_t*)(Psb + rm * 72 + kk * 16 + 2 * tg + 8);
            pa[3] = *(const uint32_t*)(Psb + (rm + 8) * 72 + kk * 16 + 2 * tg + 8);
#pragma unroll
            for (int p = 0; p < 4; p++) {
                uint32_t b0, b1, b2, b3;
                int krow = kk * 16 + lmh * 8 + lr;
                int ncol = p * 16 + lkh * 8;
                ldm_x4t(b0, b1, b2, b3,
                        sptr(VsB + st * 4608 + krow * 72 + ncol));
                mma16(of[2 * p],     pa, b0, b1);
                mma16(of[2 * p + 1], pa, b2, b3);
            }
        }
        __syncthreads();
    }
#undef LOAD_KV

    float inv_lo = 1.f / l_lo, inv_hi = 1.f / l_hi;
    size_t r_lo = brow + qt * 128 + rm;
    size_t r_hi = r_lo + 8;
#pragma unroll
    for (int nt = 0; nt < 8; nt++) {
        size_t col = hcol + nt * 8 + 2 * tg;
        *(__half2*)(O + r_lo * Dv + col) =
            __floats2half2_rn(of[nt][0] * inv_lo, of[nt][1] * inv_lo);
        *(__half2*)(O + r_hi * Dv + col) =
            __floats2half2_rn(of[nt][2] * inv_hi, of[nt][3] * inv_hi);
    }
}

// ---------------------------------------------------------------------------
// LayerNorm finalize (32 partials per batch) + apply
// ---------------------------------------------------------------------------
__global__ void ln_finalize32(const float* __restrict__ part,
                              float* __restrict__ stats)
{
    const int b = blockIdx.x;
    const int t = threadIdx.x;    // 32
    float s  = part[(b * 32 + t) * 2 + 0];
    float s2 = part[(b * 32 + t) * 2 + 1];
#pragma unroll
    for (int m = 16; m; m >>= 1) {
        s  += __shfl_xor_sync(0xffffffffu, s, m);
        s2 += __shfl_xor_sync(0xffffffffu, s2, m);
    }
    if (t == 0) {
        float n = (float)SDv;
        float mean = s / n;
        float var  = s2 / n - mean * mean;
        stats[b * 2 + 0] = mean;
        stats[b * 2 + 1] = rsqrtf(var + 1e-5f);
    }
}

template <int HALF_COPY>
__global__ void __launch_bounds__(256) ln_apply(
    const float* __restrict__ R, const float* __restrict__ stats,
    const float* __restrict__ W, const float* __restrict__ Bb,
    float* __restrict__ out, __half* __restrict__ outh)
{
    size_t i4 = (size_t)blockIdx.x * 256 + threadIdx.x;
    size_t e  = i4 * 4;
    int b  = (int)(e >> 19);
    int sd = (int)(e & (SDv - 1));
    float mean = stats[b * 2 + 0];
    float rstd = stats[b * 2 + 1];
    float4 r  = *(const float4*)(R + e);
    float4 w4 = *(const float4*)(W + sd);
    float4 b4 = *(const float4*)(Bb + sd);
    float4 y;
    y.x = (r.x - mean) * rstd * w4.x + b4.x;
    y.y = (r.y - mean) * rstd * w4.y + b4.y;
    y.z = (r.z - mean) * rstd * w4.z + b4.z;
    y.w = (r.w - mean) * rstd * w4.w + b4.w;
    *(float4*)(out + e) = y;
    if (HALF_COPY) {
        *(__half2*)(outh + e)     = __floats2half2_rn(y.x, y.y);
        *(__half2*)(outh + e + 2) = __floats2half2_rn(y.z, y.w);
    }
}

// ---------------------------------------------------------------------------
extern "C" void kernel_launch(void* const* d_in, const int* in_sizes, int n_in,
                              void* d_out, int out_size)
{
    const float* x    = (const float*)d_in[0];
    const float* mask = (const float*)d_in[1];
    const float* wq   = (const float*)d_in[2];
    const float* bq   = (const float*)d_in[3];
    const float* wk   = (const float*)d_in[4];
    const float* bk   = (const float*)d_in[5];
    const float* wv   = (const float*)d_in[6];
    const float* bv   = (const float*)d_in[7];
    const float* wo   = (const float*)d_in[8];
    const float* bo   = (const float*)d_in[9];
    const float* w1   = (const float*)d_in[10];
    const float* b1   = (const float*)d_in[11];
    const float* w2   = (const float*)d_in[12];
    const float* b2   = (const float*)d_in[13];
    const float* ln1w = (const float*)d_in[14];
    const float* ln1b = (const float*)d_in[15];
    const float* ln2w = (const float*)d_in[16];
    const float* ln2b = (const float*)d_in[17];
    float* out = (float*)d_out;

    void* p;
    cudaGetSymbolAddress(&p, g_xh);      __half* xh    = (__half*)p;
    cudaGetSymbolAddress(&p, g_qkvh);    __half* qkvh  = (__half*)p;
    cudaGetSymbolAddress(&p, g_ctxh);    __half* ctxh  = (__half*)p;
    cudaGetSymbolAddress(&p, g_o1h);     __half* o1h   = (__half*)p;
    cudaGetSymbolAddress(&p, g_ffnh);    __half* ffnh  = (__half*)p;
    cudaGetSymbolAddress(&p, g_wqkvh);   __half* wqkvh = (__half*)p;
    cudaGetSymbolAddress(&p, g_woh);     __half* woh   = (__half*)p;
    cudaGetSymbolAddress(&p, g_w1h);     __half* w1h   = (__half*)p;
    cudaGetSymbolAddress(&p, g_w2h);     __half* w2h   = (__half*)p;
    cudaGetSymbolAddress(&p, g_bqkv);    float* bqkv   = (float*)p;
    cudaGetSymbolAddress(&p, g_res1);    float* res1   = (float*)p;
    cudaGetSymbolAddress(&p, g_out1);    float* out1   = (float*)p;
    cudaGetSymbolAddress(&p, g_res2);    float* res2   = (float*)p;
    cudaGetSymbolAddress(&p, g_part1);   float* part1  = (float*)p;
    cudaGetSymbolAddress(&p, g_part2);   float* part2  = (float*)p;
    cudaGetSymbolAddress(&p, g_stats1);  float* stats1 = (float*)p;
    cudaGetSymbolAddress(&p, g_stats2);  float* stats2 = (float*)p;

    cudaFuncSetAttribute(attn_h,
                         cudaFuncAttributeMaxDynamicSharedMemorySize, ATT_SMEM);
    cudaFuncSetAttribute(gemm_h<0, 1, 0>,
                         cudaFuncAttributeMaxDynamicSharedMemorySize, GEMM_SMEM);
    cudaFuncSetAttribute(gemm_h<0, 0, 1>,
                         cudaFuncAttributeMaxDynamicSharedMemorySize, GEMM_SMEM);
    cudaFuncSetAttribute(gemm_h<1, 1, 0>,
                         cudaFuncAttributeMaxDynamicSharedMemorySize, GEMM_SMEM);

    dim3 blk(256);
    dim3 gQKV(QS / 128, BSv / 128);    // (12, 128)
    dim3 gD(Dv / 128, BSv / 128);      // (4, 128)
    dim3 gF(DFFv / 128, BSv / 128);    // (16, 128)
    dim3 gAttn(Sv / 128, Bv * 8);      // (8, 128)
    int  gApply = (BSv * Dv / 4) / 256;

    // one fused conversion / packing kernel
    prep<<<11265, 256>>>(x, wq, wk, wv, wo, w1, w2, bq, bk, bv,
                         xh, wqkvh, woh, w1h, w2h, bqkv);

    // fused QKV projection (half out, packed)
    gemm_h<0, 1, 0><<<gQKV, blk, GEMM_SMEM>>>(xh, wqkvh, bqkv, nullptr, qkvh,
                                              nullptr, nullptr, QS, Dv);

    // attention
    attn_h<<<gAttn, blk, ATT_SMEM>>>(qkvh, mask, ctxh);

    // O-projection fused with residual + LN1 partials
    gemm_h<0, 0, 1><<<gD, blk, GEMM_SMEM>>>(ctxh, woh, bo, res1, nullptr,
                                            x, part1, Dv, Dv);
    ln_finalize32<<<Bv, 32>>>(part1, stats1);
    ln_apply<1><<<gApply, blk>>>(res1, stats1, ln1w, ln1b, out1, o1h);

    // FFN1 (half out)
    gemm_h<1, 1, 0><<<gF, blk, GEMM_SMEM>>>(o1h, w1h, b1, nullptr, ffnh,
                                            nullptr, nullptr, DFFv, Dv);
    // FFN2 fused with residual + LN2 partials
    gemm_h<0, 0, 1><<<gD, blk, GEMM_SMEM>>>(ffnh, w2h, b2, res2, nullptr,
                                            out1, part2, Dv, DFFv);
    ln_finalize32<<<Bv, 32>>>(part2, stats2);
    ln_apply<0><<<gApply, blk>>>(res2, stats2, ln2w, ln2b, out, nullptr);
}